// round 6
// baseline (speedup 1.0000x reference)
#include <cuda_runtime.h>
#include <cstdint>

// ---------------------------------------------------------------------------
// S = q @ k^T  [8192,8192];  G = gelu_exact(S/||S||_row*sqrt(8192));
// out = G @ v  [8192,1024].
// tf32 mma.sync + cp.async 3-stage pipeline. Operands staged in global
// pre-rounded to tf32 (cvt.rna) and k-QUAD-permuted: each 16-k group stored
// as pos 4t+j = k_{t+4j}. One LDS.128 then feeds a thread's fragments for
// TWO k-steps (A: rows r/r+8; B: one column) -> 12 LDS.128 + 32 HMMA per
// 16-k chunk. SLD=48 words makes all LDS.128 patterns conflict-free.
// CTA: 512 threads, tile 256x128, 3 stages (221 KB smem).
// ---------------------------------------------------------------------------

static __device__ float g_S [8192ull * 8192ull];  // 256 MB scores/gated (perm16 cols)
static __device__ float g_VT[1024ull * 8192ull];  // 32 MB  v^T (rounded, perm16)
static __device__ float g_QT[8192ull * 1024ull];  // 32 MB  q  (rounded, perm16)
static __device__ float g_KT[8192ull * 1024ull];  // 32 MB  k  (rounded, perm16)

__device__ __forceinline__ float f2tf32f(float x) {
    uint32_t u;
    asm("cvt.rna.tf32.f32 %0, %1;" : "=r"(u) : "f"(x));
    return __uint_as_float(u);
}

// ---------------------------------------------------------------------------
// GEMM: C[M,N] = A[M,K] * B[N,K]^T, operands tf32-valued & k-quad-permuted.
// Block 256x128x32, 16 warps (8M x 2N), warp tile 32x64.
// ---------------------------------------------------------------------------
constexpr int BM = 256, BN = 128, BK = 32;
constexpr int SLD = 48;                  // SLD/4 == 12 ≡ 4 (mod 8): LDS.128 conflict-free
constexpr int STAGES = 3;
constexpr int TILEA = BM * SLD;          // 12288 floats
constexpr int TILEB = BN * SLD;          // 6144 floats
constexpr int STAGE = TILEA + TILEB;     // 18432 floats
constexpr unsigned SMEM_BYTES = STAGES * STAGE * 4;  // 221184 B

__device__ __forceinline__ void cp16(uint32_t dst_s, const float* src) {
    asm volatile("cp.async.cg.shared.global [%0], [%1], 16;\n" :: "r"(dst_s), "l"(src));
}

__device__ __forceinline__ void mma_tf32(float* d, uint32_t a0, uint32_t a1,
                                         uint32_t a2, uint32_t a3,
                                         uint32_t b0, uint32_t b1) {
    asm volatile(
        "mma.sync.aligned.m16n8k8.row.col.f32.tf32.tf32.f32 "
        "{%0,%1,%2,%3}, {%4,%5,%6,%7}, {%8,%9}, {%0,%1,%2,%3};\n"
        : "+f"(d[0]), "+f"(d[1]), "+f"(d[2]), "+f"(d[3])
        : "r"(a0), "r"(a1), "r"(a2), "r"(a3), "r"(b0), "r"(b1));
}

template <bool PERMC>
__global__ __launch_bounds__(512, 1) void gemm_tf32_pipe(
    const float* __restrict__ A, const float* __restrict__ B, float* __restrict__ C,
    int M, int N, int K)
{
    extern __shared__ float smem[];
    const uint32_t smem_s = (uint32_t)__cvta_generic_to_shared(smem);

    const int tid  = threadIdx.x;
    const int lane = tid & 31;
    const int wid  = tid >> 5;
    const int wm   = wid & 7;     // 0..7 along M
    const int wn   = wid >> 3;    // 0..1 along N
    const long bm = (long)blockIdx.y * BM;
    const long bn = (long)blockIdx.x * BN;

    float acc[2][8][4];
#pragma unroll
    for (int i = 0; i < 2; i++)
#pragma unroll
        for (int j = 0; j < 8; j++)
#pragma unroll
            for (int c = 0; c < 4; c++) acc[i][j][c] = 0.f;

    const int nk = K / BK;

    auto load_stage = [&](int s, int kt) {
        const uint32_t sA = smem_s + (uint32_t)(s * STAGE) * 4u;
        const uint32_t sB = sA + (uint32_t)TILEA * 4u;
        const int k0 = kt * BK;
#pragma unroll
        for (int i = 0; i < 4; i++) {              // A: 256 rows x 32 floats
            int idx = tid + i * 512;               // 0..2047
            int row = idx >> 3;
            int c4  = (idx & 7) << 2;
            cp16(sA + (uint32_t)(row * SLD + c4) * 4u,
                 &A[(size_t)(bm + row) * K + k0 + c4]);
        }
#pragma unroll
        for (int i = 0; i < 2; i++) {              // B: 128 rows x 32 floats
            int idx = tid + i * 512;               // 0..1023
            int row = idx >> 3;
            int c4  = (idx & 7) << 2;
            cp16(sB + (uint32_t)(row * SLD + c4) * 4u,
                 &B[(size_t)(bn + row) * K + k0 + c4]);
        }
        asm volatile("cp.async.commit_group;\n");
    };

#pragma unroll
    for (int s = 0; s < STAGES - 1; s++) load_stage(s, s);

    const int t    = lane & 3;
    const int qrow = lane >> 2;

    for (int kt = 0; kt < nk; kt++) {
        asm volatile("cp.async.wait_group %0;\n" :: "n"(STAGES - 2));
        __syncthreads();

        if (kt + STAGES - 1 < nk) {
            load_stage((kt + STAGES - 1) % STAGES, kt + STAGES - 1);
        } else {
            asm volatile("cp.async.commit_group;\n");
        }

        const float* As = smem + (kt % STAGES) * STAGE;
        const float* Bs = As + TILEA;

#pragma unroll
        for (int kq = 0; kq < 2; kq++) {           // two 16-k chunks per kt
            const int kb = kq * 16 + 4 * t;
            // A fragments: one float4 covers both k-steps of this chunk
            float4 va[2], va8[2];
#pragma unroll
            for (int mt = 0; mt < 2; mt++) {
                int r = wm * 32 + mt * 16 + qrow;
                va[mt]  = *reinterpret_cast<const float4*>(&As[(r    ) * SLD + kb]);
                va8[mt] = *reinterpret_cast<const float4*>(&As[(r + 8) * SLD + kb]);
            }
            // B in two batches of 4 columns to bound register pressure
#pragma unroll
            for (int half = 0; half < 2; half++) {
                float4 vb[4];
#pragma unroll
                for (int i = 0; i < 4; i++) {
                    int nt = half * 4 + i;
                    int cidx = wn * 64 + nt * 8 + qrow;
                    vb[i] = *reinterpret_cast<const float4*>(&Bs[cidx * SLD + kb]);
                }
#pragma unroll
                for (int i = 0; i < 4; i++) {
                    int nt = half * 4 + i;
#pragma unroll
                    for (int mt = 0; mt < 2; mt++) {
                        // k-step 0 of chunk: (k_t, k_{t+4}) = (.x, .y)
                        mma_tf32(acc[mt][nt],
                                 __float_as_uint(va[mt].x),  __float_as_uint(va8[mt].x),
                                 __float_as_uint(va[mt].y),  __float_as_uint(va8[mt].y),
                                 __float_as_uint(vb[i].x),   __float_as_uint(vb[i].y));
                        // k-step 1 of chunk: (k_{t+8}, k_{t+12}) = (.z, .w)
                        mma_tf32(acc[mt][nt],
                                 __float_as_uint(va[mt].z),  __float_as_uint(va8[mt].z),
                                 __float_as_uint(va[mt].w),  __float_as_uint(va8[mt].w),
                                 __float_as_uint(vb[i].z),   __float_as_uint(vb[i].w));
                    }
                }
            }
        }
    }

    // ---- epilogue ----
    // Logical col within an 8-group for lane t: c0=2t, c1=2t+1.
    // perm16 position: pos = 4*(c&3) + (c>>2); with h = nt&1 adding 8 to c.
    // => p(c0) = (t&1)*8 + (t>>1) + 2h,  p(c1) = p(c0) + 4.
#pragma unroll
    for (int mt = 0; mt < 2; mt++) {
        long r0 = bm + wm * 32 + mt * 16 + qrow;
#pragma unroll
        for (int nt = 0; nt < 8; nt++) {
            if (PERMC) {
                long base16 = bn + wn * 64 + (nt >> 1) * 16;
                int  p0 = ((t & 1) << 3) + (t >> 1) + ((nt & 1) << 1);
                C[(size_t)r0 * N + base16 + p0]           = acc[mt][nt][0];
                C[(size_t)r0 * N + base16 + p0 + 4]       = acc[mt][nt][1];
                C[(size_t)(r0 + 8) * N + base16 + p0]     = acc[mt][nt][2];
                C[(size_t)(r0 + 8) * N + base16 + p0 + 4] = acc[mt][nt][3];
            } else {
                long c0 = bn + wn * 64 + nt * 8 + 2 * t;
                *reinterpret_cast<float2*>(&C[(size_t)r0 * N + c0]) =
                    make_float2(acc[mt][nt][0], acc[mt][nt][1]);
                *reinterpret_cast<float2*>(&C[(size_t)(r0 + 8) * N + c0]) =
                    make_float2(acc[mt][nt][2], acc[mt][nt][3]);
            }
        }
    }
}

// ---------------------------------------------------------------------------
// Stage q/k: tf32-round + k-quad-permute (16-group: pos 4t+j = k_{t+4j}).
// One thread per 16-float group.
// ---------------------------------------------------------------------------
__global__ __launch_bounds__(256) void stage_quads_kernel(
    const float4* __restrict__ in, float4* __restrict__ out, int ngroups)
{
    int g = blockIdx.x * 256 + threadIdx.x;
    if (g >= ngroups) return;
    float4 a = in[4 * g + 0];   // k0..k3
    float4 b = in[4 * g + 1];   // k4..k7
    float4 c = in[4 * g + 2];   // k8..k11
    float4 d = in[4 * g + 3];   // k12..k15
    out[4 * g + 0] = make_float4(f2tf32f(a.x), f2tf32f(b.x), f2tf32f(c.x), f2tf32f(d.x));
    out[4 * g + 1] = make_float4(f2tf32f(a.y), f2tf32f(b.y), f2tf32f(c.y), f2tf32f(d.y));
    out[4 * g + 2] = make_float4(f2tf32f(a.z), f2tf32f(b.z), f2tf32f(c.z), f2tf32f(d.z));
    out[4 * g + 3] = make_float4(f2tf32f(a.w), f2tf32f(b.w), f2tf32f(c.w), f2tf32f(d.w));
}

// ---------------------------------------------------------------------------
// Row L2-norm * sqrt(N) + exact GELU in place; output tf32-rounded.
// (S columns perm16'd; norm is permutation-invariant, GELU elementwise.)
// ---------------------------------------------------------------------------
__global__ __launch_bounds__(256) void norm_gelu_kernel(float* __restrict__ S, int N)
{
    float4* p = reinterpret_cast<float4*>(S + (size_t)blockIdx.x * N);
    const int n4 = N >> 2;
    float ss = 0.f;
    for (int i = threadIdx.x; i < n4; i += 256) {
        float4 x = p[i];
        ss += x.x * x.x + x.y * x.y + x.z * x.z + x.w * x.w;
    }
    __shared__ float red[8];
#pragma unroll
    for (int o = 16; o > 0; o >>= 1) ss += __shfl_xor_sync(0xffffffffu, ss, o);
    if ((threadIdx.x & 31) == 0) red[threadIdx.x >> 5] = ss;
    __syncthreads();
    if (threadIdx.x < 32) {
        float v = (threadIdx.x < 8) ? red[threadIdx.x] : 0.f;
#pragma unroll
        for (int o = 4; o > 0; o >>= 1) v += __shfl_xor_sync(0xffffffffu, v, o);
        if (threadIdx.x == 0) red[0] = v;
    }
    __syncthreads();
    const float scale = sqrtf((float)N / red[0]);
    const float inv_sqrt2 = 0.70710678118654752440f;
    for (int i = threadIdx.x; i < n4; i += 256) {
        float4 x = p[i];
        x.x *= scale; x.y *= scale; x.z *= scale; x.w *= scale;
        x.x = f2tf32f(0.5f * x.x * (1.f + erff(x.x * inv_sqrt2)));
        x.y = f2tf32f(0.5f * x.y * (1.f + erff(x.y * inv_sqrt2)));
        x.z = f2tf32f(0.5f * x.z * (1.f + erff(x.z * inv_sqrt2)));
        x.w = f2tf32f(0.5f * x.w * (1.f + erff(x.w * inv_sqrt2)));
        p[i] = x;
    }
}

// ---------------------------------------------------------------------------
// Transpose v[8192,1024] -> vT[1024,8192], tf32-rounded + k-quad-permuted.
// ---------------------------------------------------------------------------
__global__ __launch_bounds__(256) void transpose_kernel(
    const float* __restrict__ V, float* __restrict__ VT, int R, int Ccols)
{
    __shared__ float tbuf[32][33];
    int c0 = blockIdx.x * 32, r0 = blockIdx.y * 32;
    int x = threadIdx.x, y = threadIdx.y;  // block (32,8)
#pragma unroll
    for (int j = 0; j < 32; j += 8)
        tbuf[y + j][x] = V[(size_t)(r0 + y + j) * Ccols + c0 + x];
    __syncthreads();
    int xg = x & 15;
    int px = (x & ~15) + ((xg & 3) << 2) + (xg >> 2);   // pos = 4*(c&3) + (c>>2)
#pragma unroll
    for (int j = 0; j < 32; j += 8)
        VT[(size_t)(c0 + y + j) * R + r0 + px] = f2tf32f(tbuf[x][y + j]);
}

// ---------------------------------------------------------------------------
extern "C" void kernel_launch(void* const* d_in, const int* in_sizes, int n_in,
                              void* d_out, int out_size)
{
    const float* q = (const float*)d_in[0];   // [8192, 1024]
    const float* k = (const float*)d_in[1];   // [8192, 1024]
    const float* v = (const float*)d_in[2];   // [8192, 1024]
    float* out = (float*)d_out;               // [8192, 1024]

    float *S, *VT, *QT, *KT;
    cudaGetSymbolAddress((void**)&S,  g_S);
    cudaGetSymbolAddress((void**)&VT, g_VT);
    cudaGetSymbolAddress((void**)&QT, g_QT);
    cudaGetSymbolAddress((void**)&KT, g_KT);

    static bool attr_done = false;
    if (!attr_done) {
        cudaFuncSetAttribute(gemm_tf32_pipe<true>,
                             cudaFuncAttributeMaxDynamicSharedMemorySize, SMEM_BYTES);
        cudaFuncSetAttribute(gemm_tf32_pipe<false>,
                             cudaFuncAttributeMaxDynamicSharedMemorySize, SMEM_BYTES);
        attr_done = true;
    }

    const int M = 8192, NBANK = 8192, D = 1024;
    const int ngroups = (M * D) / 16;

    stage_quads_kernel<<<(ngroups + 255) / 256, 256>>>((const float4*)q, (float4*)QT, ngroups);
    stage_quads_kernel<<<(ngroups + 255) / 256, 256>>>((const float4*)k, (float4*)KT, ngroups);
    transpose_kernel<<<dim3(D / 32, NBANK / 32), dim3(32, 8)>>>(v, VT, NBANK, D);

    // S = q @ k^T  (columns stored perm16'd = GEMM2's k layout)
    gemm_tf32_pipe<true><<<dim3(NBANK / BN, M / BM), 512, SMEM_BYTES>>>(QT, KT, S, M, NBANK, D);

    // norm + exact gelu in place (tf32-rounded output)
    norm_gelu_kernel<<<M, 256>>>(S, NBANK);

    // out = G @ vT^T
    gemm_tf32_pipe<false><<<dim3(D / BN, M / BM), 512, SMEM_BYTES>>>(S, VT, out, M, D, NBANK);
}

// round 7
// speedup vs baseline: 1.7186x; 1.7186x over previous
#include <cuda_runtime.h>
#include <cstdint>

// ---------------------------------------------------------------------------
// S = q @ k^T  [8192,8192];  G = gelu_exact(S/||S||_row*sqrt(8192));
// out = G @ v  [8192,1024].
// tf32 mma.sync + cp.async 3-stage pipeline. Operands staged in global
// pre-rounded to tf32 (cvt.rna) and k-pair-permuted (8-groups stored as
// k0,k4,k1,k5,k2,k6,k3,k7) so fragment loads are LDS.64, zero cvt inline.
// SLD=40 words: conflict-free LDS.64.
// CTA: 256 threads, 8 warps (4M x 2N), warp tile 64x64, tile 256x128.
// 256 regs/thread budget -> explicit DOUBLE-BUFFERED fragments: load
// kstep+1 while MMAs of kstep issue (breaks the LDS/MMA phase-locking
// that capped tensor pipe at ~49%).
// ---------------------------------------------------------------------------

static __device__ float g_S [8192ull * 8192ull];  // 256 MB scores/gated (perm cols)
static __device__ float g_VT[1024ull * 8192ull];  // 32 MB  v^T (rounded, perm)
static __device__ float g_QT[8192ull * 1024ull];  // 32 MB  q  (rounded, perm)
static __device__ float g_KT[8192ull * 1024ull];  // 32 MB  k  (rounded, perm)

__device__ __forceinline__ float f2tf32f(float x) {
    uint32_t u;
    asm("cvt.rna.tf32.f32 %0, %1;" : "=r"(u) : "f"(x));
    return __uint_as_float(u);
}

constexpr int BM = 256, BN = 128, BK = 32;
constexpr int SLD = 40;                  // conflict-free stride for LDS.64
constexpr int STAGES = 3;
constexpr int TILEA = BM * SLD;          // 10240 floats
constexpr int TILEB = BN * SLD;          // 5120 floats
constexpr int STAGE = TILEA + TILEB;     // 15360 floats
constexpr unsigned SMEM_BYTES = STAGES * STAGE * 4;  // 184320 B

__device__ __forceinline__ void cp16(uint32_t dst_s, const float* src) {
    asm volatile("cp.async.cg.shared.global [%0], [%1], 16;\n" :: "r"(dst_s), "l"(src));
}

__device__ __forceinline__ void mma_tf32(float* d, float2 pa, float2 pa8, float2 pb) {
    asm volatile(
        "mma.sync.aligned.m16n8k8.row.col.f32.tf32.tf32.f32 "
        "{%0,%1,%2,%3}, {%4,%5,%6,%7}, {%8,%9}, {%0,%1,%2,%3};\n"
        : "+f"(d[0]), "+f"(d[1]), "+f"(d[2]), "+f"(d[3])
        : "r"(__float_as_uint(pa.x)), "r"(__float_as_uint(pa8.x)),
          "r"(__float_as_uint(pa.y)), "r"(__float_as_uint(pa8.y)),
          "r"(__float_as_uint(pb.x)), "r"(__float_as_uint(pb.y)));
}

struct Frag {
    float2 a[4];    // A rows r+0 per mt
    float2 a8[4];   // A rows r+8 per mt
    float2 b[8];    // B per nt
};

template <bool PERMC>
__global__ __launch_bounds__(256, 1) void gemm_tf32_pipe(
    const float* __restrict__ A, const float* __restrict__ B, float* __restrict__ C,
    int M, int N, int K)
{
    extern __shared__ float smem[];
    const uint32_t smem_s = (uint32_t)__cvta_generic_to_shared(smem);

    const int tid  = threadIdx.x;
    const int lane = tid & 31;
    const int wid  = tid >> 5;
    const int wm   = wid & 3;     // 0..3 along M (64 rows each)
    const int wn   = wid >> 2;    // 0..1 along N (64 cols each)
    const long bm = (long)blockIdx.y * BM;
    const long bn = (long)blockIdx.x * BN;

    float acc[4][8][4];
#pragma unroll
    for (int i = 0; i < 4; i++)
#pragma unroll
        for (int j = 0; j < 8; j++)
#pragma unroll
            for (int c = 0; c < 4; c++) acc[i][j][c] = 0.f;

    const int nk = K / BK;

    auto load_stage = [&](int s, int kt) {
        const uint32_t sA = smem_s + (uint32_t)(s * STAGE) * 4u;
        const uint32_t sB = sA + (uint32_t)TILEA * 4u;
        const int k0 = kt * BK;
#pragma unroll
        for (int i = 0; i < 8; i++) {              // A: 256 rows x 32 floats
            int idx = tid + i * 256;               // 0..2047
            int row = idx >> 3;
            int c4  = (idx & 7) << 2;
            cp16(sA + (uint32_t)(row * SLD + c4) * 4u,
                 &A[(size_t)(bm + row) * K + k0 + c4]);
        }
#pragma unroll
        for (int i = 0; i < 4; i++) {              // B: 128 rows x 32 floats
            int idx = tid + i * 256;               // 0..1023
            int row = idx >> 3;
            int c4  = (idx & 7) << 2;
            cp16(sB + (uint32_t)(row * SLD + c4) * 4u,
                 &B[(size_t)(bn + row) * K + k0 + c4]);
        }
        asm volatile("cp.async.commit_group;\n");
    };

#pragma unroll
    for (int s = 0; s < STAGES - 1; s++) load_stage(s, s);

    const int t    = lane & 3;
    const int tk2  = t * 2;
    const int qrow = lane >> 2;

    Frag f[2];

    auto load_frags = [&](const float* As, const float* Bs, int ks, Frag& F) {
        const int kk = ks * 8 + tk2;
#pragma unroll
        for (int mt = 0; mt < 4; mt++) {
            int r = wm * 64 + mt * 16 + qrow;
            F.a[mt]  = *reinterpret_cast<const float2*>(&As[(r    ) * SLD + kk]);
            F.a8[mt] = *reinterpret_cast<const float2*>(&As[(r + 8) * SLD + kk]);
        }
#pragma unroll
        for (int nt = 0; nt < 8; nt++) {
            int cidx = wn * 64 + nt * 8 + qrow;
            F.b[nt] = *reinterpret_cast<const float2*>(&Bs[cidx * SLD + kk]);
        }
    };

    auto mma_all = [&](const Frag& F) {
#pragma unroll
        for (int nt = 0; nt < 8; nt++)
#pragma unroll
            for (int mt = 0; mt < 4; mt++)
                mma_tf32(acc[mt][nt], F.a[mt], F.a8[mt], F.b[nt]);
    };

    for (int kt = 0; kt < nk; kt++) {
        asm volatile("cp.async.wait_group %0;\n" :: "n"(STAGES - 2));
        __syncthreads();

        if (kt + STAGES - 1 < nk) {
            load_stage((kt + STAGES - 1) % STAGES, kt + STAGES - 1);
        } else {
            asm volatile("cp.async.commit_group;\n");
        }

        const float* As = smem + (kt % STAGES) * STAGE;
        const float* Bs = As + TILEA;

        load_frags(As, Bs, 0, f[0]);
#pragma unroll
        for (int ks = 0; ks < 4; ks++) {
            if (ks < 3) load_frags(As, Bs, ks + 1, f[(ks + 1) & 1]);
            mma_all(f[ks & 1]);
        }
    }

    // ---- epilogue ----
    // pair-permuted position of logical col 2t within its 8-group; col 2t+1 -> +2
    const int p0 = (t < 2) ? 4 * t : 4 * t - 7;
#pragma unroll
    for (int mt = 0; mt < 4; mt++) {
        long r0 = bm + wm * 64 + mt * 16 + qrow;
#pragma unroll
        for (int nt = 0; nt < 8; nt++) {
            long base = bn + wn * 64 + nt * 8;
            if (PERMC) {
                C[(size_t)r0 * N + base + p0]            = acc[mt][nt][0];
                C[(size_t)r0 * N + base + p0 + 2]        = acc[mt][nt][1];
                C[(size_t)(r0 + 8) * N + base + p0]      = acc[mt][nt][2];
                C[(size_t)(r0 + 8) * N + base + p0 + 2]  = acc[mt][nt][3];
            } else {
                long c0 = base + 2 * t;
                *reinterpret_cast<float2*>(&C[(size_t)r0 * N + c0]) =
                    make_float2(acc[mt][nt][0], acc[mt][nt][1]);
                *reinterpret_cast<float2*>(&C[(size_t)(r0 + 8) * N + c0]) =
                    make_float2(acc[mt][nt][2], acc[mt][nt][3]);
            }
        }
    }
}

// ---------------------------------------------------------------------------
// Stage q/k: tf32-round + k-pair-permute (8-group -> k0,k4,k1,k5,k2,k6,k3,k7)
// ---------------------------------------------------------------------------
__global__ __launch_bounds__(256) void stage_pairs_kernel(
    const float4* __restrict__ in, float4* __restrict__ out, int ngroups)
{
    int g = blockIdx.x * 256 + threadIdx.x;
    if (g >= ngroups) return;
    float4 a = in[2 * g];       // k0..k3
    float4 b = in[2 * g + 1];   // k4..k7
    out[2 * g]     = make_float4(f2tf32f(a.x), f2tf32f(b.x), f2tf32f(a.y), f2tf32f(b.y));
    out[2 * g + 1] = make_float4(f2tf32f(a.z), f2tf32f(b.z), f2tf32f(a.w), f2tf32f(b.w));
}

// ---------------------------------------------------------------------------
// Row L2-norm * sqrt(N) + exact GELU in place; output tf32-rounded.
// ---------------------------------------------------------------------------
__global__ __launch_bounds__(256) void norm_gelu_kernel(float* __restrict__ S, int N)
{
    float4* p = reinterpret_cast<float4*>(S + (size_t)blockIdx.x * N);
    const int n4 = N >> 2;
    float ss = 0.f;
    for (int i = threadIdx.x; i < n4; i += 256) {
        float4 x = p[i];
        ss += x.x * x.x + x.y * x.y + x.z * x.z + x.w * x.w;
    }
    __shared__ float red[8];
#pragma unroll
    for (int o = 16; o > 0; o >>= 1) ss += __shfl_xor_sync(0xffffffffu, ss, o);
    if ((threadIdx.x & 31) == 0) red[threadIdx.x >> 5] = ss;
    __syncthreads();
    if (threadIdx.x < 32) {
        float v = (threadIdx.x < 8) ? red[threadIdx.x] : 0.f;
#pragma unroll
        for (int o = 4; o > 0; o >>= 1) v += __shfl_xor_sync(0xffffffffu, v, o);
        if (threadIdx.x == 0) red[0] = v;
    }
    __syncthreads();
    const float scale = sqrtf((float)N / red[0]);
    const float inv_sqrt2 = 0.70710678118654752440f;
    for (int i = threadIdx.x; i < n4; i += 256) {
        float4 x = p[i];
        x.x *= scale; x.y *= scale; x.z *= scale; x.w *= scale;
        x.x = f2tf32f(0.5f * x.x * (1.f + erff(x.x * inv_sqrt2)));
        x.y = f2tf32f(0.5f * x.y * (1.f + erff(x.y * inv_sqrt2)));
        x.z = f2tf32f(0.5f * x.z * (1.f + erff(x.z * inv_sqrt2)));
        x.w = f2tf32f(0.5f * x.w * (1.f + erff(x.w * inv_sqrt2)));
        p[i] = x;
    }
}

// ---------------------------------------------------------------------------
// Transpose v[8192,1024] -> vT[1024,8192], tf32-rounded + k-pair-permuted.
// ---------------------------------------------------------------------------
__global__ __launch_bounds__(256) void transpose_kernel(
    const float* __restrict__ V, float* __restrict__ VT, int R, int Ccols)
{
    __shared__ float tbuf[32][33];
    int c0 = blockIdx.x * 32, r0 = blockIdx.y * 32;
    int x = threadIdx.x, y = threadIdx.y;  // block (32,8)
#pragma unroll
    for (int j = 0; j < 32; j += 8)
        tbuf[y + j][x] = V[(size_t)(r0 + y + j) * Ccols + c0 + x];
    __syncthreads();
    int xg = x & 7;
    int px = (x & ~7) + ((xg & 3) << 1) + (xg >> 2);
#pragma unroll
    for (int j = 0; j < 32; j += 8)
        VT[(size_t)(c0 + y + j) * R + r0 + px] = f2tf32f(tbuf[x][y + j]);
}

// ---------------------------------------------------------------------------
extern "C" void kernel_launch(void* const* d_in, const int* in_sizes, int n_in,
                              void* d_out, int out_size)
{
    const float* q = (const float*)d_in[0];   // [8192, 1024]
    const float* k = (const float*)d_in[1];   // [8192, 1024]
    const float* v = (const float*)d_in[2];   // [8192, 1024]
    float* out = (float*)d_out;               // [8192, 1024]

    float *S, *VT, *QT, *KT;
    cudaGetSymbolAddress((void**)&S,  g_S);
    cudaGetSymbolAddress((void**)&VT, g_VT);
    cudaGetSymbolAddress((void**)&QT, g_QT);
    cudaGetSymbolAddress((void**)&KT, g_KT);

    static bool attr_done = false;
    if (!attr_done) {
        cudaFuncSetAttribute(gemm_tf32_pipe<true>,
                             cudaFuncAttributeMaxDynamicSharedMemorySize, SMEM_BYTES);
        cudaFuncSetAttribute(gemm_tf32_pipe<false>,
                             cudaFuncAttributeMaxDynamicSharedMemorySize, SMEM_BYTES);
        attr_done = true;
    }

    const int M = 8192, NBANK = 8192, D = 1024;
    const int ngroups = (M * D) / 8;

    stage_pairs_kernel<<<(ngroups + 255) / 256, 256>>>((const float4*)q, (float4*)QT, ngroups);
    stage_pairs_kernel<<<(ngroups + 255) / 256, 256>>>((const float4*)k, (float4*)KT, ngroups);
    transpose_kernel<<<dim3(D / 32, NBANK / 32), dim3(32, 8)>>>(v, VT, NBANK, D);

    // S = q @ k^T  (columns stored pair-permuted = GEMM2's k layout)
    gemm_tf32_pipe<true><<<dim3(NBANK / BN, M / BM), 256, SMEM_BYTES>>>(QT, KT, S, M, NBANK, D);

    // norm + exact gelu in place (tf32-rounded output)
    norm_gelu_kernel<<<M, 256>>>(S, NBANK);

    // out = G @ vT^T
    gemm_tf32_pipe<false><<<dim3(D / BN, M / BM), 256, SMEM_BYTES>>>(S, VT, out, M, D, NBANK);
}

// round 8
// speedup vs baseline: 1.7727x; 1.0315x over previous
#include <cuda_runtime.h>
#include <cstdint>

// ---------------------------------------------------------------------------
// S = q @ k^T  [8192,8192];  G = gelu_exact(S/||S||_row*sqrt(8192));
// out = G @ v  [8192,1024].
// tf32 mma.sync (saturated at ~152 TF/s = tf32 HW roofline for legacy HMMA).
// This round: GEMM2 split-K x4 (fixes 2-wave quantization), row-sumsq fused
// into GEMM1 epilogue (saves a 256MB pass), deterministic partial sums.
// ---------------------------------------------------------------------------

static __device__ float g_S [8192ull * 8192ull];      // 256 MB scores/gated (perm cols)
static __device__ float g_VT[1024ull * 8192ull];      // 32 MB  v^T (rounded, perm)
static __device__ float g_QT[8192ull * 1024ull];      // 32 MB  q  (rounded, perm)
static __device__ float g_KT[8192ull * 1024ull];      // 32 MB  k  (rounded, perm)
static __device__ float g_P [4ull * 8192ull * 1024ull]; // 128 MB split-K partials
static __device__ float g_SQ[8192ull * 128ull];       // 4 MB per-(row, ctaCol) sumsq

__device__ __forceinline__ float f2tf32f(float x) {
    uint32_t u;
    asm("cvt.rna.tf32.f32 %0, %1;" : "=r"(u) : "f"(x));
    return __uint_as_float(u);
}

constexpr int BM = 256, BN = 128, BK = 32;
constexpr int SLD = 40;                  // conflict-free stride for LDS.64
constexpr int STAGES = 3;
constexpr int TILEA = BM * SLD;
constexpr int TILEB = BN * SLD;
constexpr int STAGE = TILEA + TILEB;
constexpr unsigned SMEM_BYTES = STAGES * STAGE * 4;  // 184320 B

__device__ __forceinline__ void cp16(uint32_t dst_s, const float* src) {
    asm volatile("cp.async.cg.shared.global [%0], [%1], 16;\n" :: "r"(dst_s), "l"(src));
}

__device__ __forceinline__ void mma_tf32(float* d, float2 pa, float2 pa8, float2 pb) {
    asm volatile(
        "mma.sync.aligned.m16n8k8.row.col.f32.tf32.tf32.f32 "
        "{%0,%1,%2,%3}, {%4,%5,%6,%7}, {%8,%9}, {%0,%1,%2,%3};\n"
        : "+f"(d[0]), "+f"(d[1]), "+f"(d[2]), "+f"(d[3])
        : "r"(__float_as_uint(pa.x)), "r"(__float_as_uint(pa8.x)),
          "r"(__float_as_uint(pa.y)), "r"(__float_as_uint(pa8.y)),
          "r"(__float_as_uint(pb.x)), "r"(__float_as_uint(pb.y)));
}

struct Frag {
    float2 a[4];
    float2 a8[4];
    float2 b[8];
};

// ---------------------------------------------------------------------------
// GEMM: C[M,N] (+= per-z partial) = A[M,K]*B[N,K]^T, pair-permuted tf32 vals.
// grid.z = split-K chunks; each writes its own C buffer slice (C + z*M*N).
// WSQ: also emit per-(row, ctaCol) sum of squares (for GEMM1 -> row norms).
// ---------------------------------------------------------------------------
template <bool PERMC, bool WSQ>
__global__ __launch_bounds__(256, 1) void gemm_tf32_pipe(
    const float* __restrict__ A, const float* __restrict__ B, float* __restrict__ C,
    float* __restrict__ sqpart,
    int M, int N, int kcount, int strideA, int strideB)
{
    extern __shared__ float smem[];
    const uint32_t smem_s = (uint32_t)__cvta_generic_to_shared(smem);

    const int tid  = threadIdx.x;
    const int lane = tid & 31;
    const int wid  = tid >> 5;
    const int wm   = wid & 3;     // 0..3 along M (64 rows each)
    const int wn   = wid >> 2;    // 0..1 along N (64 cols each)
    const long bm = (long)blockIdx.y * BM;
    const long bn = (long)blockIdx.x * BN;
    const int kbase = blockIdx.z * kcount;
    C += (size_t)blockIdx.z * M * (size_t)N;

    float acc[4][8][4];
#pragma unroll
    for (int i = 0; i < 4; i++)
#pragma unroll
        for (int j = 0; j < 8; j++)
#pragma unroll
            for (int c = 0; c < 4; c++) acc[i][j][c] = 0.f;

    const int nk = kcount / BK;

    auto load_stage = [&](int s, int kt) {
        const uint32_t sA = smem_s + (uint32_t)(s * STAGE) * 4u;
        const uint32_t sB = sA + (uint32_t)TILEA * 4u;
        const int k0 = kbase + kt * BK;
#pragma unroll
        for (int i = 0; i < 8; i++) {              // A: 256 rows x 32 floats
            int idx = tid + i * 256;
            int row = idx >> 3;
            int c4  = (idx & 7) << 2;
            cp16(sA + (uint32_t)(row * SLD + c4) * 4u,
                 &A[(size_t)(bm + row) * strideA + k0 + c4]);
        }
#pragma unroll
        for (int i = 0; i < 4; i++) {              // B: 128 rows x 32 floats
            int idx = tid + i * 256;
            int row = idx >> 3;
            int c4  = (idx & 7) << 2;
            cp16(sB + (uint32_t)(row * SLD + c4) * 4u,
                 &B[(size_t)(bn + row) * strideB + k0 + c4]);
        }
        asm volatile("cp.async.commit_group;\n");
    };

#pragma unroll
    for (int s = 0; s < STAGES - 1; s++) load_stage(s, s);

    const int t    = lane & 3;
    const int tk2  = t * 2;
    const int qrow = lane >> 2;

    Frag f[2];

    auto load_frags = [&](const float* As, const float* Bs, int ks, Frag& F) {
        const int kk = ks * 8 + tk2;
#pragma unroll
        for (int mt = 0; mt < 4; mt++) {
            int r = wm * 64 + mt * 16 + qrow;
            F.a[mt]  = *reinterpret_cast<const float2*>(&As[(r    ) * SLD + kk]);
            F.a8[mt] = *reinterpret_cast<const float2*>(&As[(r + 8) * SLD + kk]);
        }
#pragma unroll
        for (int nt = 0; nt < 8; nt++) {
            int cidx = wn * 64 + nt * 8 + qrow;
            F.b[nt] = *reinterpret_cast<const float2*>(&Bs[cidx * SLD + kk]);
        }
    };

    auto mma_all = [&](const Frag& F) {
#pragma unroll
        for (int nt = 0; nt < 8; nt++)
#pragma unroll
            for (int mt = 0; mt < 4; mt++)
                mma_tf32(acc[mt][nt], F.a[mt], F.a8[mt], F.b[nt]);
    };

    for (int kt = 0; kt < nk; kt++) {
        asm volatile("cp.async.wait_group %0;\n" :: "n"(STAGES - 2));
        __syncthreads();

        if (kt + STAGES - 1 < nk) {
            load_stage((kt + STAGES - 1) % STAGES, kt + STAGES - 1);
        } else {
            asm volatile("cp.async.commit_group;\n");
        }

        const float* As = smem + (kt % STAGES) * STAGE;
        const float* Bs = As + TILEA;

        load_frags(As, Bs, 0, f[0]);
#pragma unroll
        for (int ks = 0; ks < 4; ks++) {
            if (ks < 3) load_frags(As, Bs, ks + 1, f[(ks + 1) & 1]);
            mma_all(f[ks & 1]);
        }
    }

    // ---- fused per-row sumsq (warp-local 64 cols -> deterministic slot) ----
    if (WSQ) {
        const int pidx = blockIdx.x * 2 + wn;     // 0..127
#pragma unroll
        for (int mt = 0; mt < 4; mt++) {
            float s0 = 0.f, s1 = 0.f;
#pragma unroll
            for (int nt = 0; nt < 8; nt++) {
                s0 += acc[mt][nt][0] * acc[mt][nt][0] + acc[mt][nt][1] * acc[mt][nt][1];
                s1 += acc[mt][nt][2] * acc[mt][nt][2] + acc[mt][nt][3] * acc[mt][nt][3];
            }
            s0 += __shfl_xor_sync(0xffffffffu, s0, 1);
            s0 += __shfl_xor_sync(0xffffffffu, s0, 2);
            s1 += __shfl_xor_sync(0xffffffffu, s1, 1);
            s1 += __shfl_xor_sync(0xffffffffu, s1, 2);
            if (t == 0) {
                long r = bm + wm * 64 + mt * 16 + qrow;
                sqpart[(size_t)r * 128 + pidx]       = s0;
                sqpart[(size_t)(r + 8) * 128 + pidx] = s1;
            }
        }
    }

    // ---- epilogue stores ----
    const int p0 = (t < 2) ? 4 * t : 4 * t - 7;
#pragma unroll
    for (int mt = 0; mt < 4; mt++) {
        long r0 = bm + wm * 64 + mt * 16 + qrow;
#pragma unroll
        for (int nt = 0; nt < 8; nt++) {
            long base = bn + wn * 64 + nt * 8;
            if (PERMC) {
                C[(size_t)r0 * N + base + p0]            = acc[mt][nt][0];
                C[(size_t)r0 * N + base + p0 + 2]        = acc[mt][nt][1];
                C[(size_t)(r0 + 8) * N + base + p0]      = acc[mt][nt][2];
                C[(size_t)(r0 + 8) * N + base + p0 + 2]  = acc[mt][nt][3];
            } else {
                long c0 = base + 2 * t;
                *reinterpret_cast<float2*>(&C[(size_t)r0 * N + c0]) =
                    make_float2(acc[mt][nt][0], acc[mt][nt][1]);
                *reinterpret_cast<float2*>(&C[(size_t)(r0 + 8) * N + c0]) =
                    make_float2(acc[mt][nt][2], acc[mt][nt][3]);
            }
        }
    }
}

// ---------------------------------------------------------------------------
// Stage q/k: tf32-round + k-pair-permute (8-group -> k0,k4,k1,k5,k2,k6,k3,k7)
// ---------------------------------------------------------------------------
__global__ __launch_bounds__(256) void stage_pairs_kernel(
    const float4* __restrict__ in, float4* __restrict__ out, int ngroups)
{
    int g = blockIdx.x * 256 + threadIdx.x;
    if (g >= ngroups) return;
    float4 a = in[2 * g];
    float4 b = in[2 * g + 1];
    out[2 * g]     = make_float4(f2tf32f(a.x), f2tf32f(b.x), f2tf32f(a.y), f2tf32f(b.y));
    out[2 * g + 1] = make_float4(f2tf32f(a.z), f2tf32f(b.z), f2tf32f(a.w), f2tf32f(b.w));
}

// ---------------------------------------------------------------------------
// Row scale from precomputed sumsq partials, then exact GELU in place.
// ---------------------------------------------------------------------------
__global__ __launch_bounds__(256) void norm_gelu_kernel(
    float* __restrict__ S, const float* __restrict__ sqpart, int N)
{
    const int row = blockIdx.x;
    float ss = (threadIdx.x < 128) ? sqpart[(size_t)row * 128 + threadIdx.x] : 0.f;
    __shared__ float red[8];
#pragma unroll
    for (int o = 16; o > 0; o >>= 1) ss += __shfl_xor_sync(0xffffffffu, ss, o);
    if ((threadIdx.x & 31) == 0) red[threadIdx.x >> 5] = ss;
    __syncthreads();
    if (threadIdx.x < 32) {
        float v = (threadIdx.x < 8) ? red[threadIdx.x] : 0.f;
#pragma unroll
        for (int o = 4; o > 0; o >>= 1) v += __shfl_xor_sync(0xffffffffu, v, o);
        if (threadIdx.x == 0) red[0] = v;
    }
    __syncthreads();
    const float scale = sqrtf((float)N / red[0]);
    const float inv_sqrt2 = 0.70710678118654752440f;
    float4* p = reinterpret_cast<float4*>(S + (size_t)row * N);
    const int n4 = N >> 2;
    for (int i = threadIdx.x; i < n4; i += 256) {
        float4 x = p[i];
        x.x *= scale; x.y *= scale; x.z *= scale; x.w *= scale;
        x.x = f2tf32f(0.5f * x.x * (1.f + erff(x.x * inv_sqrt2)));
        x.y = f2tf32f(0.5f * x.y * (1.f + erff(x.y * inv_sqrt2)));
        x.z = f2tf32f(0.5f * x.z * (1.f + erff(x.z * inv_sqrt2)));
        x.w = f2tf32f(0.5f * x.w * (1.f + erff(x.w * inv_sqrt2)));
        p[i] = x;
    }
}

// ---------------------------------------------------------------------------
// Transpose v[8192,1024] -> vT[1024,8192], tf32-rounded + k-pair-permuted.
// ---------------------------------------------------------------------------
__global__ __launch_bounds__(256) void transpose_kernel(
    const float* __restrict__ V, float* __restrict__ VT, int R, int Ccols)
{
    __shared__ float tbuf[32][33];
    int c0 = blockIdx.x * 32, r0 = blockIdx.y * 32;
    int x = threadIdx.x, y = threadIdx.y;
#pragma unroll
    for (int j = 0; j < 32; j += 8)
        tbuf[y + j][x] = V[(size_t)(r0 + y + j) * Ccols + c0 + x];
    __syncthreads();
    int xg = x & 7;
    int px = (x & ~7) + ((xg & 3) << 1) + (xg >> 2);
#pragma unroll
    for (int j = 0; j < 32; j += 8)
        VT[(size_t)(c0 + y + j) * R + r0 + px] = f2tf32f(tbuf[x][y + j]);
}

// ---------------------------------------------------------------------------
// Sum 4 split-K partials -> out (deterministic order).
// ---------------------------------------------------------------------------
__global__ __launch_bounds__(256) void sum4_kernel(
    const float4* __restrict__ p, float4* __restrict__ out, int n4, size_t stride4)
{
    int i = blockIdx.x * 256 + threadIdx.x;
    if (i >= n4) return;
    float4 a = p[i], b = p[i + stride4], c = p[i + 2 * stride4], d = p[i + 3 * stride4];
    out[i] = make_float4((a.x + b.x) + (c.x + d.x),
                         (a.y + b.y) + (c.y + d.y),
                         (a.z + b.z) + (c.z + d.z),
                         (a.w + b.w) + (c.w + d.w));
}

// ---------------------------------------------------------------------------
extern "C" void kernel_launch(void* const* d_in, const int* in_sizes, int n_in,
                              void* d_out, int out_size)
{
    const float* q = (const float*)d_in[0];   // [8192, 1024]
    const float* k = (const float*)d_in[1];   // [8192, 1024]
    const float* v = (const float*)d_in[2];   // [8192, 1024]
    float* out = (float*)d_out;               // [8192, 1024]

    float *S, *VT, *QT, *KT, *P, *SQ;
    cudaGetSymbolAddress((void**)&S,  g_S);
    cudaGetSymbolAddress((void**)&VT, g_VT);
    cudaGetSymbolAddress((void**)&QT, g_QT);
    cudaGetSymbolAddress((void**)&KT, g_KT);
    cudaGetSymbolAddress((void**)&P,  g_P);
    cudaGetSymbolAddress((void**)&SQ, g_SQ);

    static bool attr_done = false;
    if (!attr_done) {
        cudaFuncSetAttribute((const void*)gemm_tf32_pipe<true, true>,
                             cudaFuncAttributeMaxDynamicSharedMemorySize, SMEM_BYTES);
        cudaFuncSetAttribute((const void*)gemm_tf32_pipe<false, false>,
                             cudaFuncAttributeMaxDynamicSharedMemorySize, SMEM_BYTES);
        attr_done = true;
    }

    const int M = 8192, NBANK = 8192, D = 1024;
    const int ngroups = (M * D) / 8;
    const int KCHUNK = 2048;                   // split-K x4 for GEMM2

    stage_pairs_kernel<<<(ngroups + 255) / 256, 256>>>((const float4*)q, (float4*)QT, ngroups);
    stage_pairs_kernel<<<(ngroups + 255) / 256, 256>>>((const float4*)k, (float4*)KT, ngroups);
    transpose_kernel<<<dim3(D / 32, NBANK / 32), dim3(32, 8)>>>(v, VT, NBANK, D);

    // S = q @ k^T (perm cols), fused row-sumsq partials
    gemm_tf32_pipe<true, true><<<dim3(NBANK / BN, M / BM, 1), 256, SMEM_BYTES>>>(
        QT, KT, S, SQ, M, NBANK, D, D, D);

    // scale + exact gelu in place (reads precomputed sumsq)
    norm_gelu_kernel<<<M, 256>>>(S, SQ, NBANK);

    // out partials = G @ vT^T, split-K x4 (grid.z = chunk)
    gemm_tf32_pipe<false, false><<<dim3(D / BN, M / BM, 4), 256, SMEM_BYTES>>>(
        S, VT, P, nullptr, M, D, KCHUNK, NBANK, NBANK);

    // out = sum of 4 partials
    const int n4 = (M * D) / 4;
    sum4_kernel<<<(n4 + 255) / 256, 256>>>((const float4*)P, (float4*)out, n4,
                                           (size_t)M * D / 4);
}

// round 10
// speedup vs baseline: 2.2945x; 1.2943x over previous
#include <cuda_runtime.h>
#include <cuda_fp16.h>
#include <cstdint>

// ---------------------------------------------------------------------------
// S = q @ k^T  [8192,8192] (tf32 mma.sync, ~152 TF/s ceiling measured);
// G = gelu_exact(S/||S||_row*sqrt(8192))  -> fp16, P2-permuted;
// out = G @ v  (fp16 m16n8k16 mma.sync: half the instructions of tf32).
// GEMM1: pair-permuted tf32 (P1), fused row-sumsq. GEMM2: fp16, split-K x4.
// ---------------------------------------------------------------------------

static __device__ float  g_S  [8192ull * 8192ull];    // 256 MB scores (P1 cols)
static __device__ __half g_Gh [8192ull * 8192ull];    // 128 MB gated fp16 (P2 cols)
static __device__ __half g_VTh[1024ull * 8192ull];    // 16 MB  v^T fp16 (P2 k)
static __device__ float  g_QT [8192ull * 1024ull];    // 32 MB  q  (tf32, P1)
static __device__ float  g_KT [8192ull * 1024ull];    // 32 MB  k  (tf32, P1)
static __device__ float  g_P  [4ull * 8192ull * 1024ull]; // 128 MB split-K partials
static __device__ float  g_SQ [8192ull * 128ull];     // 4 MB sumsq partials

__device__ __forceinline__ float f2tf32f(float x) {
    uint32_t u;
    asm("cvt.rna.tf32.f32 %0, %1;" : "=r"(u) : "f"(x));
    return __uint_as_float(u);
}

__device__ __forceinline__ void cp16(uint32_t dst_s, const void* src) {
    asm volatile("cp.async.cg.shared.global [%0], [%1], 16;\n" :: "r"(dst_s), "l"(src));
}

// =============================== GEMM1: tf32 ===============================
constexpr int BM = 256, BN = 128, BK = 32;
constexpr int SLD = 40;
constexpr int STAGES = 3;
constexpr int TILEA = BM * SLD;
constexpr int TILEB = BN * SLD;
constexpr int STAGE = TILEA + TILEB;
constexpr unsigned SMEM_BYTES = STAGES * STAGE * 4;  // 184320 B

__device__ __forceinline__ void mma_tf32(float* d, float2 pa, float2 pa8, float2 pb) {
    asm volatile(
        "mma.sync.aligned.m16n8k8.row.col.f32.tf32.tf32.f32 "
        "{%0,%1,%2,%3}, {%4,%5,%6,%7}, {%8,%9}, {%0,%1,%2,%3};\n"
        : "+f"(d[0]), "+f"(d[1]), "+f"(d[2]), "+f"(d[3])
        : "r"(__float_as_uint(pa.x)), "r"(__float_as_uint(pa8.x)),
          "r"(__float_as_uint(pa.y)), "r"(__float_as_uint(pa8.y)),
          "r"(__float_as_uint(pb.x)), "r"(__float_as_uint(pb.y)));
}

struct Frag {
    float2 a[4];
    float2 a8[4];
    float2 b[8];
};

__global__ __launch_bounds__(256, 1) void gemm1_tf32(
    const float* __restrict__ A, const float* __restrict__ B, float* __restrict__ C,
    float* __restrict__ sqpart, int M, int N, int K)
{
    extern __shared__ float smem[];
    const uint32_t smem_s = (uint32_t)__cvta_generic_to_shared(smem);

    const int tid  = threadIdx.x;
    const int lane = tid & 31;
    const int wid  = tid >> 5;
    const int wm   = wid & 3;
    const int wn   = wid >> 2;
    const long bm = (long)blockIdx.y * BM;
    const long bn = (long)blockIdx.x * BN;

    float acc[4][8][4];
#pragma unroll
    for (int i = 0; i < 4; i++)
#pragma unroll
        for (int j = 0; j < 8; j++)
#pragma unroll
            for (int c = 0; c < 4; c++) acc[i][j][c] = 0.f;

    const int nk = K / BK;

    auto load_stage = [&](int s, int kt) {
        const uint32_t sA = smem_s + (uint32_t)(s * STAGE) * 4u;
        const uint32_t sB = sA + (uint32_t)TILEA * 4u;
        const int k0 = kt * BK;
#pragma unroll
        for (int i = 0; i < 8; i++) {
            int idx = tid + i * 256;
            int row = idx >> 3;
            int c4  = (idx & 7) << 2;
            cp16(sA + (uint32_t)(row * SLD + c4) * 4u,
                 &A[(size_t)(bm + row) * K + k0 + c4]);
        }
#pragma unroll
        for (int i = 0; i < 4; i++) {
            int idx = tid + i * 256;
            int row = idx >> 3;
            int c4  = (idx & 7) << 2;
            cp16(sB + (uint32_t)(row * SLD + c4) * 4u,
                 &B[(size_t)(bn + row) * K + k0 + c4]);
        }
        asm volatile("cp.async.commit_group;\n");
    };

#pragma unroll
    for (int s = 0; s < STAGES - 1; s++) load_stage(s, s);

    const int t    = lane & 3;
    const int tk2  = t * 2;
    const int qrow = lane >> 2;

    Frag f[2];

    auto load_frags = [&](const float* As, const float* Bs, int ks, Frag& F) {
        const int kk = ks * 8 + tk2;
#pragma unroll
        for (int mt = 0; mt < 4; mt++) {
            int r = wm * 64 + mt * 16 + qrow;
            F.a[mt]  = *reinterpret_cast<const float2*>(&As[(r    ) * SLD + kk]);
            F.a8[mt] = *reinterpret_cast<const float2*>(&As[(r + 8) * SLD + kk]);
        }
#pragma unroll
        for (int nt = 0; nt < 8; nt++) {
            int cidx = wn * 64 + nt * 8 + qrow;
            F.b[nt] = *reinterpret_cast<const float2*>(&Bs[cidx * SLD + kk]);
        }
    };

    auto mma_all = [&](const Frag& F) {
#pragma unroll
        for (int nt = 0; nt < 8; nt++)
#pragma unroll
            for (int mt = 0; mt < 4; mt++)
                mma_tf32(acc[mt][nt], F.a[mt], F.a8[mt], F.b[nt]);
    };

    for (int kt = 0; kt < nk; kt++) {
        asm volatile("cp.async.wait_group %0;\n" :: "n"(STAGES - 2));
        __syncthreads();

        if (kt + STAGES - 1 < nk) {
            load_stage((kt + STAGES - 1) % STAGES, kt + STAGES - 1);
        } else {
            asm volatile("cp.async.commit_group;\n");
        }

        const float* As = smem + (kt % STAGES) * STAGE;
        const float* Bs = As + TILEA;

        load_frags(As, Bs, 0, f[0]);
#pragma unroll
        for (int ks = 0; ks < 4; ks++) {
            if (ks < 3) load_frags(As, Bs, ks + 1, f[(ks + 1) & 1]);
            mma_all(f[ks & 1]);
        }
    }

    // fused per-row sumsq (deterministic slot per (row, ctaCol-half))
    {
        const int pidx = blockIdx.x * 2 + wn;
#pragma unroll
        for (int mt = 0; mt < 4; mt++) {
            float s0 = 0.f, s1 = 0.f;
#pragma unroll
            for (int nt = 0; nt < 8; nt++) {
                s0 += acc[mt][nt][0] * acc[mt][nt][0] + acc[mt][nt][1] * acc[mt][nt][1];
                s1 += acc[mt][nt][2] * acc[mt][nt][2] + acc[mt][nt][3] * acc[mt][nt][3];
            }
            s0 += __shfl_xor_sync(0xffffffffu, s0, 1);
            s0 += __shfl_xor_sync(0xffffffffu, s0, 2);
            s1 += __shfl_xor_sync(0xffffffffu, s1, 1);
            s1 += __shfl_xor_sync(0xffffffffu, s1, 2);
            if (t == 0) {
                long r = bm + wm * 64 + mt * 16 + qrow;
                sqpart[(size_t)r * 128 + pidx]       = s0;
                sqpart[(size_t)(r + 8) * 128 + pidx] = s1;
            }
        }
    }

    // epilogue: P1-permuted stores
    const int p0 = (t < 2) ? 4 * t : 4 * t - 7;
#pragma unroll
    for (int mt = 0; mt < 4; mt++) {
        long r0 = bm + wm * 64 + mt * 16 + qrow;
#pragma unroll
        for (int nt = 0; nt < 8; nt++) {
            long base = bn + wn * 64 + nt * 8;
            C[(size_t)r0 * N + base + p0]            = acc[mt][nt][0];
            C[(size_t)r0 * N + base + p0 + 2]        = acc[mt][nt][1];
            C[(size_t)(r0 + 8) * N + base + p0]      = acc[mt][nt][2];
            C[(size_t)(r0 + 8) * N + base + p0 + 2]  = acc[mt][nt][3];
        }
    }
}

// =============================== GEMM2: fp16 ===============================
constexpr int BKH  = 64;                 // halves per k-iter (128 B rows)
constexpr int SLDH = 80;                 // halves; 8B-pair stride 20 ≡ 4 mod 16
constexpr int TILEAH = BM * SLDH;        // halves
constexpr int TILEBH = BN * SLDH;
constexpr int STAGEH = TILEAH + TILEBH;
constexpr unsigned SMEMH_BYTES = STAGES * STAGEH * 2;  // 184320 B

__device__ __forceinline__ void mma_f16(float* d, uint2 a, uint2 a8, uint2 b) {
    asm volatile(
        "mma.sync.aligned.m16n8k16.row.col.f32.f16.f16.f32 "
        "{%0,%1,%2,%3}, {%4,%5,%6,%7}, {%8,%9}, {%0,%1,%2,%3};\n"
        : "+f"(d[0]), "+f"(d[1]), "+f"(d[2]), "+f"(d[3])
        : "r"(a.x), "r"(a8.x), "r"(a.y), "r"(a8.y), "r"(b.x), "r"(b.y));
}

struct FragH {
    uint2 a[4];
    uint2 a8[4];
    uint2 b[8];
};

__global__ __launch_bounds__(256, 1) void gemm2_fp16(
    const __half* __restrict__ A, const __half* __restrict__ B, float* __restrict__ C,
    int M, int N, int kcount, int strideA, int strideB)
{
    extern __shared__ __half smh[];
    const uint32_t smem_s = (uint32_t)__cvta_generic_to_shared(smh);

    const int tid  = threadIdx.x;
    const int lane = tid & 31;
    const int wid  = tid >> 5;
    const int wm   = wid & 3;
    const int wn   = wid >> 2;
    const long bm = (long)blockIdx.y * BM;
    const long bn = (long)blockIdx.x * BN;
    const int kbase = blockIdx.z * kcount;
    C += (size_t)blockIdx.z * M * (size_t)N;

    float acc[4][8][4];
#pragma unroll
    for (int i = 0; i < 4; i++)
#pragma unroll
        for (int j = 0; j < 8; j++)
#pragma unroll
            for (int c = 0; c < 4; c++) acc[i][j][c] = 0.f;

    const int nk = kcount / BKH;

    auto load_stage = [&](int s, int kt) {
        const uint32_t sA = smem_s + (uint32_t)(s * STAGEH) * 2u;
        const uint32_t sB = sA + (uint32_t)TILEAH * 2u;
        const int k0 = kbase + kt * BKH;
#pragma unroll
        for (int i = 0; i < 8; i++) {              // A: 256 rows x 64 halves
            int idx = tid + i * 256;
            int row = idx >> 3;
            int h8  = (idx & 7) << 3;              // half offset, 8 halves=16B
            cp16(sA + (uint32_t)(row * SLDH + h8) * 2u,
                 &A[(size_t)(bm + row) * strideA + k0 + h8]);
        }
#pragma unroll
        for (int i = 0; i < 4; i++) {              // B: 128 rows x 64 halves
            int idx = tid + i * 256;
            int row = idx >> 3;
            int h8  = (idx & 7) << 3;
            cp16(sB + (uint32_t)(row * SLDH + h8) * 2u,
                 &B[(size_t)(bn + row) * strideB + k0 + h8]);
        }
        asm volatile("cp.async.commit_group;\n");
    };

#pragma unroll
    for (int s = 0; s < STAGES - 1; s++) load_stage(s, s);

    const int t    = lane & 3;
    const int qrow = lane >> 2;

    FragH f[2];

    auto load_frags = [&](const __half* As, const __half* Bs, int g, FragH& F) {
        const int kk = g * 16 + 4 * t;             // P2: slots 4t..4t+3
#pragma unroll
        for (int mt = 0; mt < 4; mt++) {
            int r = wm * 64 + mt * 16 + qrow;
            F.a[mt]  = *reinterpret_cast<const uint2*>(&As[(r    ) * SLDH + kk]);
            F.a8[mt] = *reinterpret_cast<const uint2*>(&As[(r + 8) * SLDH + kk]);
        }
#pragma unroll
        for (int nt = 0; nt < 8; nt++) {
            int cidx = wn * 64 + nt * 8 + qrow;
            F.b[nt] = *reinterpret_cast<const uint2*>(&Bs[cidx * SLDH + kk]);
        }
    };

    auto mma_all = [&](const FragH& F) {
#pragma unroll
        for (int nt = 0; nt < 8; nt++)
#pragma unroll
            for (int mt = 0; mt < 4; mt++)
                mma_f16(acc[mt][nt], F.a[mt], F.a8[mt], F.b[nt]);
    };

    for (int kt = 0; kt < nk; kt++) {
        asm volatile("cp.async.wait_group %0;\n" :: "n"(STAGES - 2));
        __syncthreads();

        if (kt + STAGES - 1 < nk) {
            load_stage((kt + STAGES - 1) % STAGES, kt + STAGES - 1);
        } else {
            asm volatile("cp.async.commit_group;\n");
        }

        const __half* As = smh + (kt % STAGES) * STAGEH;
        const __half* Bs = As + TILEAH;

        load_frags(As, Bs, 0, f[0]);
#pragma unroll
        for (int g = 0; g < 4; g++) {              // 4 x 16-k groups per kt
            if (g < 3) load_frags(As, Bs, g + 1, f[(g + 1) & 1]);
            mma_all(f[g & 1]);
        }
    }

    // epilogue: standard layout partial stores
#pragma unroll
    for (int mt = 0; mt < 4; mt++) {
        long r0 = bm + wm * 64 + mt * 16 + qrow;
#pragma unroll
        for (int nt = 0; nt < 8; nt++) {
            long c0 = bn + wn * 64 + nt * 8 + 2 * t;
            *reinterpret_cast<float2*>(&C[(size_t)r0 * N + c0]) =
                make_float2(acc[mt][nt][0], acc[mt][nt][1]);
            *reinterpret_cast<float2*>(&C[(size_t)(r0 + 8) * N + c0]) =
                make_float2(acc[mt][nt][2], acc[mt][nt][3]);
        }
    }
}

// ======================= staging / elementwise kernels =====================
__global__ __launch_bounds__(256) void stage_pairs_kernel(
    const float4* __restrict__ in, float4* __restrict__ out, int ngroups)
{
    int g = blockIdx.x * 256 + threadIdx.x;
    if (g >= ngroups) return;
    float4 a = in[2 * g];
    float4 b = in[2 * g + 1];
    out[2 * g]     = make_float4(f2tf32f(a.x), f2tf32f(b.x), f2tf32f(a.y), f2tf32f(b.y));
    out[2 * g + 1] = make_float4(f2tf32f(a.z), f2tf32f(b.z), f2tf32f(a.w), f2tf32f(b.w));
}

// norm + exact gelu: read fp32 S (P1 cols), write fp16 G (P2 cols).
__global__ __launch_bounds__(256) void norm_gelu_h_kernel(
    const float* __restrict__ S, const float* __restrict__ sqpart,
    __half* __restrict__ Gh, int N)
{
    const int row = blockIdx.x;
    float ss = (threadIdx.x < 128) ? sqpart[(size_t)row * 128 + threadIdx.x] : 0.f;
    __shared__ float red[8];
#pragma unroll
    for (int o = 16; o > 0; o >>= 1) ss += __shfl_xor_sync(0xffffffffu, ss, o);
    if ((threadIdx.x & 31) == 0) red[threadIdx.x >> 5] = ss;
    __syncthreads();
    if (threadIdx.x < 32) {
        float v = (threadIdx.x < 8) ? red[threadIdx.x] : 0.f;
#pragma unroll
        for (int o = 4; o > 0; o >>= 1) v += __shfl_xor_sync(0xffffffffu, v, o);
        if (threadIdx.x == 0) red[0] = v;
    }
    __syncthreads();
    const float scale = sqrtf((float)N / red[0]);
    const float inv_sqrt2 = 0.70710678118654752440f;

    // half slot p takes stored-S index invM[p] (P1 -> logical -> P2 fused)
    constexpr int invM[16] = {0,2,8,10,4,6,12,14,1,3,9,11,5,7,13,15};

    const float* srow = S + (size_t)row * N;
    __half* grow = Gh + (size_t)row * N;
    const int ngr = N >> 4;
    for (int gi = threadIdx.x; gi < ngr; gi += 256) {
        float x[16];
        const float4* src = reinterpret_cast<const float4*>(srow + gi * 16);
        float4 v0 = src[0], v1 = src[1], v2 = src[2], v3 = src[3];
        x[0]=v0.x; x[1]=v0.y; x[2]=v0.z; x[3]=v0.w;
        x[4]=v1.x; x[5]=v1.y; x[6]=v1.z; x[7]=v1.w;
        x[8]=v2.x; x[9]=v2.y; x[10]=v2.z; x[11]=v2.w;
        x[12]=v3.x; x[13]=v3.y; x[14]=v3.z; x[15]=v3.w;
        float gl[16];
#pragma unroll
        for (int s = 0; s < 16; s++) {
            float xs = x[s] * scale;
            gl[s] = 0.5f * xs * (1.f + erff(xs * inv_sqrt2));
        }
        uint32_t u[8];
#pragma unroll
        for (int j = 0; j < 8; j++) {
            __half2 h2 = __floats2half2_rn(gl[invM[2 * j]], gl[invM[2 * j + 1]]);
            u[j] = *reinterpret_cast<uint32_t*>(&h2);
        }
        uint4* dst = reinterpret_cast<uint4*>(grow + gi * 16);
        dst[0] = make_uint4(u[0], u[1], u[2], u[3]);
        dst[1] = make_uint4(u[4], u[5], u[6], u[7]);
    }
}

// Transpose v[8192,1024] -> vT fp16 [1024,8192], P2-permuted k.
__global__ __launch_bounds__(256) void transpose_h_kernel(
    const float* __restrict__ V, __half* __restrict__ VTh, int R, int Ccols)
{
    __shared__ float tbuf[32][33];
    int c0 = blockIdx.x * 32, r0 = blockIdx.y * 32;
    int x = threadIdx.x, y = threadIdx.y;
#pragma unroll
    for (int j = 0; j < 32; j += 8)
        tbuf[y + j][x] = V[(size_t)(r0 + y + j) * Ccols + c0 + x];
    __syncthreads();
    int k = x & 15;
    int px = (x & ~15) + 4 * ((k & 7) >> 1) + (k & 1) + 2 * (k >> 3);
#pragma unroll
    for (int j = 0; j < 32; j += 8)
        VTh[(size_t)(c0 + y + j) * R + r0 + px] = __float2half_rn(tbuf[x][y + j]);
}

__global__ __launch_bounds__(256) void sum4_kernel(
    const float4* __restrict__ p, float4* __restrict__ out, int n4, size_t stride4)
{
    int i = blockIdx.x * 256 + threadIdx.x;
    if (i >= n4) return;
    float4 a = p[i], b = p[i + stride4], c = p[i + 2 * stride4], d = p[i + 3 * stride4];
    out[i] = make_float4((a.x + b.x) + (c.x + d.x),
                         (a.y + b.y) + (c.y + d.y),
                         (a.z + b.z) + (c.z + d.z),
                         (a.w + b.w) + (c.w + d.w));
}

// ---------------------------------------------------------------------------
extern "C" void kernel_launch(void* const* d_in, const int* in_sizes, int n_in,
                              void* d_out, int out_size)
{
    const float* q = (const float*)d_in[0];
    const float* k = (const float*)d_in[1];
    const float* v = (const float*)d_in[2];
    float* out = (float*)d_out;

    float *S, *QT, *KT, *P, *SQ;
    __half *Gh, *VTh;
    cudaGetSymbolAddress((void**)&S,   g_S);
    cudaGetSymbolAddress((void**)&Gh,  g_Gh);
    cudaGetSymbolAddress((void**)&VTh, g_VTh);
    cudaGetSymbolAddress((void**)&QT,  g_QT);
    cudaGetSymbolAddress((void**)&KT,  g_KT);
    cudaGetSymbolAddress((void**)&P,   g_P);
    cudaGetSymbolAddress((void**)&SQ,  g_SQ);

    static bool attr_done = false;
    if (!attr_done) {
        cudaFuncSetAttribute((const void*)gemm1_tf32,
                             cudaFuncAttributeMaxDynamicSharedMemorySize, SMEM_BYTES);
        cudaFuncSetAttribute((const void*)gemm2_fp16,
                             cudaFuncAttributeMaxDynamicSharedMemorySize, SMEMH_BYTES);
        attr_done = true;
    }

    const int M = 8192, NBANK = 8192, D = 1024;
    const int ngroups = (M * D) / 8;
    const int KCHUNK = 2048;

    stage_pairs_kernel<<<(ngroups + 255) / 256, 256>>>((const float4*)q, (float4*)QT, ngroups);
    stage_pairs_kernel<<<(ngroups + 255) / 256, 256>>>((const float4*)k, (float4*)KT, ngroups);
    transpose_h_kernel<<<dim3(D / 32, NBANK / 32), dim3(32, 8)>>>(v, VTh, NBANK, D);

    // S = q @ k^T (tf32, P1 cols), fused row-sumsq
    gemm1_tf32<<<dim3(NBANK / BN, M / BM), 256, SMEM_BYTES>>>(QT, KT, S, SQ, M, NBANK, D);

    // G = gelu(scale*S) -> fp16 P2 layout
    norm_gelu_h_kernel<<<M, 256>>>(S, SQ, Gh, NBANK);

    // out partials = G @ vT^T (fp16), split-K x4
    gemm2_fp16<<<dim3(D / BN, M / BM, 4), 256, SMEMH_BYTES>>>(
        Gh, VTh, P, M, D, KCHUNK, NBANK, NBANK);

    const int n4 = (M * D) / 4;
    sum4_kernel<<<(n4 + 255) / 256, 256>>>((const float4*)P, (float4*)out, n4,
                                           (size_t)M * D / 4);
}

// round 11
// speedup vs baseline: 3.0761x; 1.3407x over previous
#include <cuda_runtime.h>
#include <cuda_fp16.h>
#include <cstdint>

// ---------------------------------------------------------------------------
// S = q @ k^T  [8192,8192];  G = gelu_exact(S/||S||_row*sqrt(8192));
// out = G @ v  [8192,1024].
// BOTH GEMMs in fp16 m16n8k16 mma.sync (fp32 accum). fp16 mantissa (11 bit)
// == tf32 mantissa, so precision matches the proven tf32 path; K=16/instr
// halves tensor-instruction count vs tf32.
// Operands staged fp16 with P2 k-permutation (16-group: slots 4t..4t+3 hold
// logical k {2t,2t+1,2t+8,2t+9}) -> every fragment load is one LDS.64.
// SLDH=80 halves: conflict-free. GEMM1 fuses row-sumsq; GEMM2 split-K x4.
// ---------------------------------------------------------------------------

static __device__ float  g_S  [8192ull * 8192ull];    // 256 MB scores (natural cols)
static __device__ __half g_Gh [8192ull * 8192ull];    // 128 MB gated fp16 (P2 cols)
static __device__ __half g_VTh[1024ull * 8192ull];    // 16 MB  v^T fp16 (P2 k)
static __device__ __half g_QTh[8192ull * 1024ull];    // 16 MB  q fp16 (P2 k)
static __device__ __half g_KTh[8192ull * 1024ull];    // 16 MB  k fp16 (P2 k)
static __device__ float  g_P  [4ull * 8192ull * 1024ull]; // 128 MB split-K partials
static __device__ float  g_SQ [8192ull * 128ull];     // 4 MB sumsq partials

__device__ __forceinline__ void cp16(uint32_t dst_s, const void* src) {
    asm volatile("cp.async.cg.shared.global [%0], [%1], 16;\n" :: "r"(dst_s), "l"(src));
}

// =========================== unified fp16 GEMM =============================
constexpr int BM = 256, BN = 128;
constexpr int BKH  = 64;                 // halves per k-iter (128 B rows)
constexpr int SLDH = 80;                 // halves; conflict-free LDS.64
constexpr int STAGES = 3;
constexpr int TILEAH = BM * SLDH;
constexpr int TILEBH = BN * SLDH;
constexpr int STAGEH = TILEAH + TILEBH;
constexpr unsigned SMEMH_BYTES = STAGES * STAGEH * 2;  // 184320 B

__device__ __forceinline__ void mma_f16(float* d, uint2 a, uint2 a8, uint2 b) {
    asm volatile(
        "mma.sync.aligned.m16n8k16.row.col.f32.f16.f16.f32 "
        "{%0,%1,%2,%3}, {%4,%5,%6,%7}, {%8,%9}, {%0,%1,%2,%3};\n"
        : "+f"(d[0]), "+f"(d[1]), "+f"(d[2]), "+f"(d[3])
        : "r"(a.x), "r"(a8.x), "r"(a.y), "r"(a8.y), "r"(b.x), "r"(b.y));
}

struct FragH {
    uint2 a[4];
    uint2 a8[4];
    uint2 b[8];
};

// C[M,N] = A[M,K]*B[N,K]^T (fp16 in, fp32 out). grid.z: split-K slice
// (separate C buffer per z). WSQ: emit per-(row, ctaCol-half) sumsq.
template <bool WSQ>
__global__ __launch_bounds__(256, 1) void gemm_fp16(
    const __half* __restrict__ A, const __half* __restrict__ B, float* __restrict__ C,
    float* __restrict__ sqpart,
    int M, int N, int kcount, int strideA, int strideB)
{
    extern __shared__ __half smh[];
    const uint32_t smem_s = (uint32_t)__cvta_generic_to_shared(smh);

    const int tid  = threadIdx.x;
    const int lane = tid & 31;
    const int wid  = tid >> 5;
    const int wm   = wid & 3;
    const int wn   = wid >> 2;
    const long bm = (long)blockIdx.y * BM;
    const long bn = (long)blockIdx.x * BN;
    const int kbase = blockIdx.z * kcount;
    C += (size_t)blockIdx.z * M * (size_t)N;

    float acc[4][8][4];
#pragma unroll
    for (int i = 0; i < 4; i++)
#pragma unroll
        for (int j = 0; j < 8; j++)
#pragma unroll
            for (int c = 0; c < 4; c++) acc[i][j][c] = 0.f;

    const int nk = kcount / BKH;

    auto load_stage = [&](int s, int kt) {
        const uint32_t sA = smem_s + (uint32_t)(s * STAGEH) * 2u;
        const uint32_t sB = sA + (uint32_t)TILEAH * 2u;
        const int k0 = kbase + kt * BKH;
#pragma unroll
        for (int i = 0; i < 8; i++) {              // A: 256 rows x 64 halves
            int idx = tid + i * 256;
            int row = idx >> 3;
            int h8  = (idx & 7) << 3;
            cp16(sA + (uint32_t)(row * SLDH + h8) * 2u,
                 &A[(size_t)(bm + row) * strideA + k0 + h8]);
        }
#pragma unroll
        for (int i = 0; i < 4; i++) {              // B: 128 rows x 64 halves
            int idx = tid + i * 256;
            int row = idx >> 3;
            int h8  = (idx & 7) << 3;
            cp16(sB + (uint32_t)(row * SLDH + h8) * 2u,
                 &B[(size_t)(bn + row) * strideB + k0 + h8]);
        }
        asm volatile("cp.async.commit_group;\n");
    };

#pragma unroll
    for (int s = 0; s < STAGES - 1; s++) load_stage(s, s);

    const int t    = lane & 3;
    const int qrow = lane >> 2;

    FragH f[2];

    auto load_frags = [&](const __half* As, const __half* Bs, int g, FragH& F) {
        const int kk = g * 16 + 4 * t;             // P2: slots 4t..4t+3
#pragma unroll
        for (int mt = 0; mt < 4; mt++) {
            int r = wm * 64 + mt * 16 + qrow;
            F.a[mt]  = *reinterpret_cast<const uint2*>(&As[(r    ) * SLDH + kk]);
            F.a8[mt] = *reinterpret_cast<const uint2*>(&As[(r + 8) * SLDH + kk]);
        }
#pragma unroll
        for (int nt = 0; nt < 8; nt++) {
            int cidx = wn * 64 + nt * 8 + qrow;
            F.b[nt] = *reinterpret_cast<const uint2*>(&Bs[cidx * SLDH + kk]);
        }
    };

    auto mma_all = [&](const FragH& F) {
#pragma unroll
        for (int nt = 0; nt < 8; nt++)
#pragma unroll
            for (int mt = 0; mt < 4; mt++)
                mma_f16(acc[mt][nt], F.a[mt], F.a8[mt], F.b[nt]);
    };

    for (int kt = 0; kt < nk; kt++) {
        asm volatile("cp.async.wait_group %0;\n" :: "n"(STAGES - 2));
        __syncthreads();

        if (kt + STAGES - 1 < nk) {
            load_stage((kt + STAGES - 1) % STAGES, kt + STAGES - 1);
        } else {
            asm volatile("cp.async.commit_group;\n");
        }

        const __half* As = smh + (kt % STAGES) * STAGEH;
        const __half* Bs = As + TILEAH;

        load_frags(As, Bs, 0, f[0]);
#pragma unroll
        for (int g = 0; g < 4; g++) {              // 4 x 16-k groups per kt
            if (g < 3) load_frags(As, Bs, g + 1, f[(g + 1) & 1]);
            mma_all(f[g & 1]);
        }
    }

    // fused per-row sumsq partials (deterministic slots)
    if (WSQ) {
        const int pidx = blockIdx.x * 2 + wn;
#pragma unroll
        for (int mt = 0; mt < 4; mt++) {
            float s0 = 0.f, s1 = 0.f;
#pragma unroll
            for (int nt = 0; nt < 8; nt++) {
                s0 += acc[mt][nt][0] * acc[mt][nt][0] + acc[mt][nt][1] * acc[mt][nt][1];
                s1 += acc[mt][nt][2] * acc[mt][nt][2] + acc[mt][nt][3] * acc[mt][nt][3];
            }
            s0 += __shfl_xor_sync(0xffffffffu, s0, 1);
            s0 += __shfl_xor_sync(0xffffffffu, s0, 2);
            s1 += __shfl_xor_sync(0xffffffffu, s1, 1);
            s1 += __shfl_xor_sync(0xffffffffu, s1, 2);
            if (t == 0) {
                long r = bm + wm * 64 + mt * 16 + qrow;
                sqpart[(size_t)r * 128 + pidx]       = s0;
                sqpart[(size_t)(r + 8) * 128 + pidx] = s1;
            }
        }
    }

    // epilogue: natural-layout float2 stores
#pragma unroll
    for (int mt = 0; mt < 4; mt++) {
        long r0 = bm + wm * 64 + mt * 16 + qrow;
#pragma unroll
        for (int nt = 0; nt < 8; nt++) {
            long c0 = bn + wn * 64 + nt * 8 + 2 * t;
            *reinterpret_cast<float2*>(&C[(size_t)r0 * N + c0]) =
                make_float2(acc[mt][nt][0], acc[mt][nt][1]);
            *reinterpret_cast<float2*>(&C[(size_t)(r0 + 8) * N + c0]) =
                make_float2(acc[mt][nt][2], acc[mt][nt][3]);
        }
    }
}

// ======================= staging / elementwise kernels =====================
// P2 within each 16-group: slot p holds logical k = invM[p].
__device__ __constant__ int c_invM[16] = {0,1,8,9,2,3,10,11,4,5,12,13,6,7,14,15};

// fp32 (natural k) -> fp16 (P2 k). One thread per 16-element group.
__global__ __launch_bounds__(256) void stage_h_kernel(
    const float4* __restrict__ in, __half* __restrict__ out, int ngroups)
{
    int g = blockIdx.x * 256 + threadIdx.x;
    if (g >= ngroups) return;
    float x[16];
    float4 v0 = in[4 * g], v1 = in[4 * g + 1], v2 = in[4 * g + 2], v3 = in[4 * g + 3];
    x[0]=v0.x; x[1]=v0.y; x[2]=v0.z; x[3]=v0.w;
    x[4]=v1.x; x[5]=v1.y; x[6]=v1.z; x[7]=v1.w;
    x[8]=v2.x; x[9]=v2.y; x[10]=v2.z; x[11]=v2.w;
    x[12]=v3.x; x[13]=v3.y; x[14]=v3.z; x[15]=v3.w;
    uint32_t u[8];
#pragma unroll
    for (int j = 0; j < 8; j++) {
        __half2 h2 = __floats2half2_rn(x[c_invM[2 * j]], x[c_invM[2 * j + 1]]);
        u[j] = *reinterpret_cast<uint32_t*>(&h2);
    }
    uint4* dst = reinterpret_cast<uint4*>(out + (size_t)g * 16);
    dst[0] = make_uint4(u[0], u[1], u[2], u[3]);
    dst[1] = make_uint4(u[4], u[5], u[6], u[7]);
}

// norm + exact gelu: read fp32 S (natural cols), write fp16 G (P2 cols).
__global__ __launch_bounds__(256) void norm_gelu_h_kernel(
    const float* __restrict__ S, const float* __restrict__ sqpart,
    __half* __restrict__ Gh, int N)
{
    const int row = blockIdx.x;
    float ss = (threadIdx.x < 128) ? sqpart[(size_t)row * 128 + threadIdx.x] : 0.f;
    __shared__ float red[8];
#pragma unroll
    for (int o = 16; o > 0; o >>= 1) ss += __shfl_xor_sync(0xffffffffu, ss, o);
    if ((threadIdx.x & 31) == 0) red[threadIdx.x >> 5] = ss;
    __syncthreads();
    if (threadIdx.x < 32) {
        float v = (threadIdx.x < 8) ? red[threadIdx.x] : 0.f;
#pragma unroll
        for (int o = 4; o > 0; o >>= 1) v += __shfl_xor_sync(0xffffffffu, v, o);
        if (threadIdx.x == 0) red[0] = v;
    }
    __syncthreads();
    const float scale = sqrtf((float)N / red[0]);
    const float inv_sqrt2 = 0.70710678118654752440f;

    const float* srow = S + (size_t)row * N;
    __half* grow = Gh + (size_t)row * N;
    const int ngr = N >> 4;
    for (int gi = threadIdx.x; gi < ngr; gi += 256) {
        float x[16];
        const float4* src = reinterpret_cast<const float4*>(srow + gi * 16);
        float4 v0 = src[0], v1 = src[1], v2 = src[2], v3 = src[3];
        x[0]=v0.x; x[1]=v0.y; x[2]=v0.z; x[3]=v0.w;
        x[4]=v1.x; x[5]=v1.y; x[6]=v1.z; x[7]=v1.w;
        x[8]=v2.x; x[9]=v2.y; x[10]=v2.z; x[11]=v2.w;
        x[12]=v3.x; x[13]=v3.y; x[14]=v3.z; x[15]=v3.w;
        float gl[16];
#pragma unroll
        for (int s = 0; s < 16; s++) {
            float xs = x[s] * scale;
            gl[s] = 0.5f * xs * (1.f + erff(xs * inv_sqrt2));
        }
        uint32_t u[8];
#pragma unroll
        for (int j = 0; j < 8; j++) {
            __half2 h2 = __floats2half2_rn(gl[c_invM[2 * j]], gl[c_invM[2 * j + 1]]);
            u[j] = *reinterpret_cast<uint32_t*>(&h2);
        }
        uint4* dst = reinterpret_cast<uint4*>(grow + gi * 16);
        dst[0] = make_uint4(u[0], u[1], u[2], u[3]);
        dst[1] = make_uint4(u[4], u[5], u[6], u[7]);
    }
}

// Transpose v[8192,1024] -> vT fp16 [1024,8192], P2-permuted k.
__global__ __launch_bounds__(256) void transpose_h_kernel(
    const float* __restrict__ V, __half* __restrict__ VTh, int R, int Ccols)
{
    __shared__ float tbuf[32][33];
    int c0 = blockIdx.x * 32, r0 = blockIdx.y * 32;
    int x = threadIdx.x, y = threadIdx.y;
#pragma unroll
    for (int j = 0; j < 32; j += 8)
        tbuf[y + j][x] = V[(size_t)(r0 + y + j) * Ccols + c0 + x];
    __syncthreads();
    int k = x & 15;
    int px = (x & ~15) + 4 * ((k & 7) >> 1) + (k & 1) + 2 * (k >> 3);
#pragma unroll
    for (int j = 0; j < 32; j += 8)
        VTh[(size_t)(c0 + y + j) * R + r0 + px] = __float2half_rn(tbuf[x][y + j]);
}

__global__ __launch_bounds__(256) void sum4_kernel(
    const float4* __restrict__ p, float4* __restrict__ out, int n4, size_t stride4)
{
    int i = blockIdx.x * 256 + threadIdx.x;
    if (i >= n4) return;
    float4 a = p[i], b = p[i + stride4], c = p[i + 2 * stride4], d = p[i + 3 * stride4];
    out[i] = make_float4((a.x + b.x) + (c.x + d.x),
                         (a.y + b.y) + (c.y + d.y),
                         (a.z + b.z) + (c.z + d.z),
                         (a.w + b.w) + (c.w + d.w));
}

// ---------------------------------------------------------------------------
extern "C" void kernel_launch(void* const* d_in, const int* in_sizes, int n_in,
                              void* d_out, int out_size)
{
    const float* q = (const float*)d_in[0];
    const float* k = (const float*)d_in[1];
    const float* v = (const float*)d_in[2];
    float* out = (float*)d_out;

    float *S, *P, *SQ;
    __half *Gh, *VTh, *QTh, *KTh;
    cudaGetSymbolAddress((void**)&S,   g_S);
    cudaGetSymbolAddress((void**)&Gh,  g_Gh);
    cudaGetSymbolAddress((void**)&VTh, g_VTh);
    cudaGetSymbolAddress((void**)&QTh, g_QTh);
    cudaGetSymbolAddress((void**)&KTh, g_KTh);
    cudaGetSymbolAddress((void**)&P,   g_P);
    cudaGetSymbolAddress((void**)&SQ,  g_SQ);

    static bool attr_done = false;
    if (!attr_done) {
        cudaFuncSetAttribute((const void*)gemm_fp16<true>,
                             cudaFuncAttributeMaxDynamicSharedMemorySize, SMEMH_BYTES);
        cudaFuncSetAttribute((const void*)gemm_fp16<false>,
                             cudaFuncAttributeMaxDynamicSharedMemorySize, SMEMH_BYTES);
        attr_done = true;
    }

    const int M = 8192, NBANK = 8192, D = 1024;
    const int ngroups = (M * D) / 16;
    const int KCHUNK = 2048;

    stage_h_kernel<<<(ngroups + 255) / 256, 256>>>((const float4*)q, QTh, ngroups);
    stage_h_kernel<<<(ngroups + 255) / 256, 256>>>((const float4*)k, KTh, ngroups);
    transpose_h_kernel<<<dim3(D / 32, NBANK / 32), dim3(32, 8)>>>(v, VTh, NBANK, D);

    // S = q @ k^T (fp16 mma, fp32 out, natural cols), fused row-sumsq
    gemm_fp16<true><<<dim3(NBANK / BN, M / BM, 1), 256, SMEMH_BYTES>>>(
        QTh, KTh, S, SQ, M, NBANK, D, D, D);

    // G = gelu(scale*S) -> fp16 P2 layout
    norm_gelu_h_kernel<<<M, 256>>>(S, SQ, Gh, NBANK);

    // out partials = G @ vT^T (fp16), split-K x4
    gemm_fp16<false><<<dim3(D / BN, M / BM, 4), 256, SMEMH_BYTES>>>(
        Gh, VTh, P, nullptr, M, D, KCHUNK, NBANK, NBANK);

    const int n4 = (M * D) / 4;
    sum4_kernel<<<(n4 + 255) / 256, 256>>>((const float4*)P, (float4*)out, n4,
                                           (size_t)M * D / 4);
}

// round 12
// speedup vs baseline: 3.1868x; 1.0360x over previous
#include <cuda_runtime.h>
#include <cuda_fp16.h>
#include <cstdint>

// ---------------------------------------------------------------------------
// S = q @ k^T  [8192,8192];  G = gelu_exact(S/||S||_row*sqrt(8192));
// out = G @ v  [8192,1024].
// Both GEMMs: fp16 m16n8k16 mma.sync, fp32 accum (fp16 mantissa == tf32).
// This round: inner loop on 32-bit shared-space addresses with explicit
// ld.shared.v2.b32; all fragment offsets compile-time constants folded into
// the LDS immediate -> removes the 44%-of-cycles integer addressing tax.
// P2 k-permutation (16-group: slots 4t..4t+3 = logical {2t,2t+1,2t+8,2t+9});
// SLDH=80 conflict-free. GEMM1 fuses row-sumsq; GEMM2 split-K x4.
// ---------------------------------------------------------------------------

static __device__ float  g_S  [8192ull * 8192ull];    // 256 MB scores (natural cols)
static __device__ __half g_Gh [8192ull * 8192ull];    // 128 MB gated fp16 (P2 cols)
static __device__ __half g_VTh[1024ull * 8192ull];    // 16 MB  v^T fp16 (P2 k)
static __device__ __half g_QTh[8192ull * 1024ull];    // 16 MB  q fp16 (P2 k)
static __device__ __half g_KTh[8192ull * 1024ull];    // 16 MB  k fp16 (P2 k)
static __device__ float  g_P  [4ull * 8192ull * 1024ull]; // 128 MB split-K partials
static __device__ float  g_SQ [8192ull * 128ull];     // 4 MB sumsq partials

__device__ __forceinline__ void cp16(uint32_t dst_s, const void* src) {
    asm volatile("cp.async.cg.shared.global [%0], [%1], 16;\n" :: "r"(dst_s), "l"(src));
}

__device__ __forceinline__ uint2 lds64(uint32_t addr) {
    uint2 r;
    asm volatile("ld.shared.v2.b32 {%0, %1}, [%2];" : "=r"(r.x), "=r"(r.y) : "r"(addr));
    return r;
}

// =========================== unified fp16 GEMM =============================
constexpr int BM = 256, BN = 128;
constexpr int BKH  = 64;                 // halves per k-iter
constexpr int SLDH = 80;                 // halves; conflict-free LDS.64
constexpr int STAGES = 3;
constexpr int TILEAH = BM * SLDH;        // 20480 halves
constexpr int TILEBH = BN * SLDH;        // 10240 halves
constexpr int STAGEH = TILEAH + TILEBH;  // 30720 halves
constexpr unsigned SMEMH_BYTES = STAGES * STAGEH * 2;  // 184320 B
constexpr int ROWB = 32 * SLDH * 2;      // 32-row byte stride in a tile
constexpr int MTB  = 16 * SLDH * 2;      // 16-row byte stride
constexpr int NTB  = 8 * SLDH * 2;       // 8-row byte stride

__device__ __forceinline__ void mma_f16(float* d, uint2 a, uint2 a8, uint2 b) {
    asm volatile(
        "mma.sync.aligned.m16n8k16.row.col.f32.f16.f16.f32 "
        "{%0,%1,%2,%3}, {%4,%5,%6,%7}, {%8,%9}, {%0,%1,%2,%3};\n"
        : "+f"(d[0]), "+f"(d[1]), "+f"(d[2]), "+f"(d[3])
        : "r"(a.x), "r"(a8.x), "r"(a.y), "r"(a8.y), "r"(b.x), "r"(b.y));
}

struct FragH {
    uint2 a[4];
    uint2 a8[4];
    uint2 b[8];
};

template <bool WSQ>
__global__ __launch_bounds__(256, 1) void gemm_fp16(
    const __half* __restrict__ A, const __half* __restrict__ B, float* __restrict__ C,
    float* __restrict__ sqpart,
    int M, int N, int kcount, int strideA, int strideB)
{
    extern __shared__ __half smh[];
    const uint32_t smem_s = (uint32_t)__cvta_generic_to_shared(smh);

    const int tid  = threadIdx.x;
    const int lane = tid & 31;
    const int wid  = tid >> 5;
    const int wm   = wid & 3;
    const int wn   = wid >> 2;
    const long bm = (long)blockIdx.y * BM;
    const long bn = (long)blockIdx.x * BN;
    const int kbase = blockIdx.z * kcount;
    C += (size_t)blockIdx.z * M * (size_t)N;

    float acc[4][8][4];
#pragma unroll
    for (int i = 0; i < 4; i++)
#pragma unroll
        for (int j = 0; j < 8; j++)
#pragma unroll
            for (int c = 0; c < 4; c++) acc[i][j][c] = 0.f;

    const int nk = kcount / BKH;

    // ---- staging: per-thread global bases + in-stage byte offsets ----
    const int rowA = tid >> 3;
    const int colh = (tid & 7) * 8;
    const __half* aG = A + (size_t)(bm + rowA) * strideA + kbase + colh;
    const __half* bG = B + (size_t)(bn + rowA) * strideB + kbase + colh;
    const uint32_t dA0 = (uint32_t)(rowA * SLDH + colh) * 2u;
    const uint32_t dB0 = (uint32_t)(TILEAH * 2) + dA0;

    auto load_stage = [&](int s, int kt) {
        const uint32_t sb = smem_s + (uint32_t)s * (STAGEH * 2);
        const __half* ak = aG + kt * BKH;
        const __half* bk = bG + kt * BKH;
#pragma unroll
        for (int i = 0; i < 8; i++)
            cp16(sb + dA0 + i * ROWB, ak + (size_t)i * 32 * strideA);
#pragma unroll
        for (int i = 0; i < 4; i++)
            cp16(sb + dB0 + i * ROWB, bk + (size_t)i * 32 * strideB);
        asm volatile("cp.async.commit_group;\n");
    };

#pragma unroll
    for (int s = 0; s < STAGES - 1; s++) load_stage(s, s);

    // ---- fragment base offsets (bytes, within a stage) ----
    const int t    = lane & 3;
    const int qrow = lane >> 2;
    const uint32_t aW0 = (uint32_t)((wm * 64 + qrow) * SLDH + 4 * t) * 2u;
    const uint32_t bW0 = (uint32_t)(TILEAH * 2) +
                         (uint32_t)((wn * 64 + qrow) * SLDH + 4 * t) * 2u;

    FragH f[2];

    auto load_frags = [&](uint32_t aW, uint32_t bW, FragH& F) {
#pragma unroll
        for (int mt = 0; mt < 4; mt++) {
            F.a[mt]  = lds64(aW + mt * MTB);
            F.a8[mt] = lds64(aW + mt * MTB + NTB);
        }
#pragma unroll
        for (int nt = 0; nt < 8; nt++)
            F.b[nt] = lds64(bW + nt * NTB);
    };

    auto mma_all = [&](const FragH& F) {
#pragma unroll
        for (int nt = 0; nt < 8; nt++)
#pragma unroll
            for (int mt = 0; mt < 4; mt++)
                mma_f16(acc[mt][nt], F.a[mt], F.a8[mt], F.b[nt]);
    };

    for (int kt = 0; kt < nk; kt++) {
        asm volatile("cp.async.wait_group %0;\n" :: "n"(STAGES - 2));
        __syncthreads();

        if (kt + STAGES - 1 < nk) {
            load_stage((kt + STAGES - 1) % STAGES, kt + STAGES - 1);
        } else {
            asm volatile("cp.async.commit_group;\n");
        }

        const uint32_t sb = smem_s + (uint32_t)(kt % STAGES) * (STAGEH * 2);
        const uint32_t aW = sb + aW0;
        const uint32_t bW = sb + bW0;

        load_frags(aW, bW, f[0]);
#pragma unroll
        for (int g = 0; g < 4; g++) {              // 4 x 16-k groups per kt
            if (g < 3) load_frags(aW + (g + 1) * 32, bW + (g + 1) * 32, f[(g + 1) & 1]);
            mma_all(f[g & 1]);
        }
    }

    // fused per-row sumsq partials (deterministic slots)
    if (WSQ) {
        const int pidx = blockIdx.x * 2 + wn;
#pragma unroll
        for (int mt = 0; mt < 4; mt++) {
            float s0 = 0.f, s1 = 0.f;
#pragma unroll
            for (int nt = 0; nt < 8; nt++) {
                s0 += acc[mt][nt][0] * acc[mt][nt][0] + acc[mt][nt][1] * acc[mt][nt][1];
                s1 += acc[mt][nt][2] * acc[mt][nt][2] + acc[mt][nt][3] * acc[mt][nt][3];
            }
            s0 += __shfl_xor_sync(0xffffffffu, s0, 1);
            s0 += __shfl_xor_sync(0xffffffffu, s0, 2);
            s1 += __shfl_xor_sync(0xffffffffu, s1, 1);
            s1 += __shfl_xor_sync(0xffffffffu, s1, 2);
            if (t == 0) {
                long r = bm + wm * 64 + mt * 16 + qrow;
                sqpart[(size_t)r * 128 + pidx]       = s0;
                sqpart[(size_t)(r + 8) * 128 + pidx] = s1;
            }
        }
    }

    // epilogue: natural-layout float2 stores
#pragma unroll
    for (int mt = 0; mt < 4; mt++) {
        long r0 = bm + wm * 64 + mt * 16 + qrow;
#pragma unroll
        for (int nt = 0; nt < 8; nt++) {
            long c0 = bn + wn * 64 + nt * 8 + 2 * t;
            *reinterpret_cast<float2*>(&C[(size_t)r0 * N + c0]) =
                make_float2(acc[mt][nt][0], acc[mt][nt][1]);
            *reinterpret_cast<float2*>(&C[(size_t)(r0 + 8) * N + c0]) =
                make_float2(acc[mt][nt][2], acc[mt][nt][3]);
        }
    }
}

// ======================= staging / elementwise kernels =====================
__device__ __constant__ int c_invM[16] = {0,1,8,9,2,3,10,11,4,5,12,13,6,7,14,15};

__global__ __launch_bounds__(256) void stage_h_kernel(
    const float4* __restrict__ in, __half* __restrict__ out, int ngroups)
{
    int g = blockIdx.x * 256 + threadIdx.x;
    if (g >= ngroups) return;
    float x[16];
    float4 v0 = in[4 * g], v1 = in[4 * g + 1], v2 = in[4 * g + 2], v3 = in[4 * g + 3];
    x[0]=v0.x; x[1]=v0.y; x[2]=v0.z; x[3]=v0.w;
    x[4]=v1.x; x[5]=v1.y; x[6]=v1.z; x[7]=v1.w;
    x[8]=v2.x; x[9]=v2.y; x[10]=v2.z; x[11]=v2.w;
    x[12]=v3.x; x[13]=v3.y; x[14]=v3.z; x[15]=v3.w;
    uint32_t u[8];
#pragma unroll
    for (int j = 0; j < 8; j++) {
        __half2 h2 = __floats2half2_rn(x[c_invM[2 * j]], x[c_invM[2 * j + 1]]);
        u[j] = *reinterpret_cast<uint32_t*>(&h2);
    }
    uint4* dst = reinterpret_cast<uint4*>(out + (size_t)g * 16);
    dst[0] = make_uint4(u[0], u[1], u[2], u[3]);
    dst[1] = make_uint4(u[4], u[5], u[6], u[7]);
}

__global__ __launch_bounds__(256) void norm_gelu_h_kernel(
    const float* __restrict__ S, const float* __restrict__ sqpart,
    __half* __restrict__ Gh, int N)
{
    const int row = blockIdx.x;
    float ss = (threadIdx.x < 128) ? sqpart[(size_t)row * 128 + threadIdx.x] : 0.f;
    __shared__ float red[8];
#pragma unroll
    for (int o = 16; o > 0; o >>= 1) ss += __shfl_xor_sync(0xffffffffu, ss, o);
    if ((threadIdx.x & 31) == 0) red[threadIdx.x >> 5] = ss;
    __syncthreads();
    if (threadIdx.x < 32) {
        float v = (threadIdx.x < 8) ? red[threadIdx.x] : 0.f;
#pragma unroll
        for (int o = 4; o > 0; o >>= 1) v += __shfl_xor_sync(0xffffffffu, v, o);
        if (threadIdx.x == 0) red[0] = v;
    }
    __syncthreads();
    const float scale = sqrtf((float)N / red[0]);
    const float inv_sqrt2 = 0.70710678118654752440f;

    const float* srow = S + (size_t)row * N;
    __half* grow = Gh + (size_t)row * N;
    const int ngr = N >> 4;
    for (int gi = threadIdx.x; gi < ngr; gi += 256) {
        float x[16];
        const float4* src = reinterpret_cast<const float4*>(srow + gi * 16);
        float4 v0 = src[0], v1 = src[1], v2 = src[2], v3 = src[3];
        x[0]=v0.x; x[1]=v0.y; x[2]=v0.z; x[3]=v0.w;
        x[4]=v1.x; x[5]=v1.y; x[6]=v1.z; x[7]=v1.w;
        x[8]=v2.x; x[9]=v2.y; x[10]=v2.z; x[11]=v2.w;
        x[12]=v3.x; x[13]=v3.y; x[14]=v3.z; x[15]=v3.w;
        float gl[16];
#pragma unroll
        for (int s = 0; s < 16; s++) {
            float xs = x[s] * scale;
            gl[s] = 0.5f * xs * (1.f + erff(xs * inv_sqrt2));
        }
        uint32_t u[8];
#pragma unroll
        for (int j = 0; j < 8; j++) {
            __half2 h2 = __floats2half2_rn(gl[c_invM[2 * j]], gl[c_invM[2 * j + 1]]);
            u[j] = *reinterpret_cast<uint32_t*>(&h2);
        }
        uint4* dst = reinterpret_cast<uint4*>(grow + gi * 16);
        dst[0] = make_uint4(u[0], u[1], u[2], u[3]);
        dst[1] = make_uint4(u[4], u[5], u[6], u[7]);
    }
}

__global__ __launch_bounds__(256) void transpose_h_kernel(
    const float* __restrict__ V, __half* __restrict__ VTh, int R, int Ccols)
{
    __shared__ float tbuf[32][33];
    int c0 = blockIdx.x * 32, r0 = blockIdx.y * 32;
    int x = threadIdx.x, y = threadIdx.y;
#pragma unroll
    for (int j = 0; j < 32; j += 8)
        tbuf[y + j][x] = V[(size_t)(r0 + y + j) * Ccols + c0 + x];
    __syncthreads();
    int k = x & 15;
    int px = (x & ~15) + 4 * ((k & 7) >> 1) + (k & 1) + 2 * (k >> 3);
#pragma unroll
    for (int j = 0; j < 32; j += 8)
        VTh[(size_t)(c0 + y + j) * R + r0 + px] = __float2half_rn(tbuf[x][y + j]);
}

__global__ __launch_bounds__(256) void sum4_kernel(
    const float4* __restrict__ p, float4* __restrict__ out, int n4, size_t stride4)
{
    int i = blockIdx.x * 256 + threadIdx.x;
    if (i >= n4) return;
    float4 a = p[i], b = p[i + stride4], c = p[i + 2 * stride4], d = p[i + 3 * stride4];
    out[i] = make_float4((a.x + b.x) + (c.x + d.x),
                         (a.y + b.y) + (c.y + d.y),
                         (a.z + b.z) + (c.z + d.z),
                         (a.w + b.w) + (c.w + d.w));
}

// ---------------------------------------------------------------------------
extern "C" void kernel_launch(void* const* d_in, const int* in_sizes, int n_in,
                              void* d_out, int out_size)
{
    const float* q = (const float*)d_in[0];
    const float* k = (const float*)d_in[1];
    const float* v = (const float*)d_in[2];
    float* out = (float*)d_out;

    float *S, *P, *SQ;
    __half *Gh, *VTh, *QTh, *KTh;
    cudaGetSymbolAddress((void**)&S,   g_S);
    cudaGetSymbolAddress((void**)&Gh,  g_Gh);
    cudaGetSymbolAddress((void**)&VTh, g_VTh);
    cudaGetSymbolAddress((void**)&QTh, g_QTh);
    cudaGetSymbolAddress((void**)&KTh, g_KTh);
    cudaGetSymbolAddress((void**)&P,   g_P);
    cudaGetSymbolAddress((void**)&SQ,  g_SQ);

    static bool attr_done = false;
    if (!attr_done) {
        cudaFuncSetAttribute((const void*)gemm_fp16<true>,
                             cudaFuncAttributeMaxDynamicSharedMemorySize, SMEMH_BYTES);
        cudaFuncSetAttribute((const void*)gemm_fp16<false>,
                             cudaFuncAttributeMaxDynamicSharedMemorySize, SMEMH_BYTES);
        attr_done = true;
    }

    const int M = 8192, NBANK = 8192, D = 1024;
    const int ngroups = (M * D) / 16;
    const int KCHUNK = 2048;

    stage_h_kernel<<<(ngroups + 255) / 256, 256>>>((const float4*)q, QTh, ngroups);
    stage_h_kernel<<<(ngroups + 255) / 256, 256>>>((const float4*)k, KTh, ngroups);
    transpose_h_kernel<<<dim3(D / 32, NBANK / 32), dim3(32, 8)>>>(v, VTh, NBANK, D);

    // S = q @ k^T (fp16 mma, fp32 out, natural cols), fused row-sumsq
    gemm_fp16<true><<<dim3(NBANK / BN, M / BM, 1), 256, SMEMH_BYTES>>>(
        QTh, KTh, S, SQ, M, NBANK, D, D, D);

    // G = gelu(scale*S) -> fp16 P2 layout
    norm_gelu_h_kernel<<<M, 256>>>(S, SQ, Gh, NBANK);

    // out partials = G @ vT^T (fp16), split-K x4
    gemm_fp16<false><<<dim3(D / BN, M / BM, 4), 256, SMEMH_BYTES>>>(
        Gh, VTh, P, nullptr, M, D, KCHUNK, NBANK, NBANK);

    const int n4 = (M * D) / 4;
    sum4_kernel<<<(n4 + 255) / 256, 256>>>((const float4*)P, (float4*)out, n4,
                                           (size_t)M * D / 4);
}